// round 8
// baseline (speedup 1.0000x reference)
#include <cuda_runtime.h>
#include <cuda_fp16.h>
#include <cstdint>
#include <math.h>

// Problem dims (fixed)
#define Bb 4
#define Ss 2048
#define Ee 512
#define Hh 1024
#define BS (Bb*Ss)
#define BE (Bb*Ee)

// fp32 scratch
__device__ float g_q [BS*Hh];
__device__ float g_kt[BS*Hh];
__device__ float g_vt[BS*Hh];
__device__ float g_ve[BE*Hh];
__device__ float g_sc[(size_t)BS*512];
__device__ float g_s0[BS];
// pre-converted (hi,lo) fp16x2 pair scratch
__device__ uint2 g_hsT[(Hh/2)*(size_t)BS];   // hs transposed  [kp][m]
__device__ uint2 g_exT[(Hh/2)*(size_t)BE];   // ext transposed [kp][m]
__device__ uint2 g_wc [3*(Hh/2)*(size_t)Hh]; // Wq,Wk,Wv paired [kp][n] (x32)
__device__ uint2 g_qT [(Hh/2)*(size_t)BS];   // q transposed   [kp][s]
__device__ uint2 g_keT[(Hh/2)*(size_t)BE];   // ke transposed  [kp][e]
__device__ uint2 g_veP[(BE/2)*(size_t)Hh];   // ve paired      [ep][h]

#define WSCALE 32.0f
#define WINV   (1.0f / 32.0f)

// Split two fp32 (consecutive k) into packed fp16x2 hi + lo. low half = x.
__device__ __forceinline__ void split2(float x, float y,
                                       uint32_t &h, uint32_t &l)
{
    asm("cvt.rn.f16x2.f32 %0, %1, %2;" : "=r"(h) : "f"(y), "f"(x));
    __half2 hv = *reinterpret_cast<__half2*>(&h);
    float2 b = __half22float2(hv);
    asm("cvt.rn.f16x2.f32 %0, %1, %2;" : "=r"(l) : "f"(y - b.y), "f"(x - b.x));
}

__device__ __forceinline__ void mma16(float* d, const uint32_t* a,
                                      const uint32_t* b)
{
    asm volatile(
        "mma.sync.aligned.m16n8k16.row.col.f32.f16.f16.f32 "
        "{%0,%1,%2,%3}, {%4,%5,%6,%7}, {%8,%9}, {%0,%1,%2,%3};"
        : "+f"(d[0]), "+f"(d[1]), "+f"(d[2]), "+f"(d[3])
        : "r"(a[0]), "r"(a[1]), "r"(a[2]), "r"(a[3]),
          "r"(b[0]), "r"(b[1]));
}

// ---------------------------------------------------------------------------
// Convert kernels
// ---------------------------------------------------------------------------
// src [K][N] f32 -> dst [K/2][N] uint2 pairs (k, k+1), scaled.
__global__ void conv_pair(const float* __restrict__ src,
                          uint2* __restrict__ dst, int N, float scale)
{
    int kp = blockIdx.y;
    int n0 = (blockIdx.x * 256 + threadIdx.x) * 4;
    if (n0 >= N) return;
    float4 r0 = *(const float4*)(src + (size_t)(2 * kp) * N + n0);
    float4 r1 = *(const float4*)(src + (size_t)(2 * kp + 1) * N + n0);
    uint2 o[4];
    split2(scale * r0.x, scale * r1.x, o[0].x, o[0].y);
    split2(scale * r0.y, scale * r1.y, o[1].x, o[1].y);
    split2(scale * r0.z, scale * r1.z, o[2].x, o[2].y);
    split2(scale * r0.w, scale * r1.w, o[3].x, o[3].y);
    uint2* d = dst + (size_t)kp * N + n0;
    *(uint4*)d       = *(uint4*)&o[0];
    *(uint4*)(d + 2) = *(uint4*)&o[2];
}

// src [M][K] f32 -> dst [K/2][M] uint2 (transpose + split). 64x64 tiles.
__global__ void conv_trans(const float* __restrict__ src,
                           uint2* __restrict__ dst, int M, int K)
{
    __shared__ float t[64][65];
    const int m0 = blockIdx.x * 64;
    const int k0 = blockIdx.y * 64;
    const int tid = threadIdx.x;
    const int mr = tid >> 2;
    const int kc = (tid & 3) * 4;
    #pragma unroll
    for (int i = 0; i < 4; i++) {
        float4 v = *(const float4*)(src + (size_t)(m0 + mr) * K
                                    + k0 + (kc + i) * 4);
        t[mr][(kc + i) * 4 + 0] = v.x;
        t[mr][(kc + i) * 4 + 1] = v.y;
        t[mr][(kc + i) * 4 + 2] = v.z;
        t[mr][(kc + i) * 4 + 3] = v.w;
    }
    __syncthreads();
    const int kp = tid >> 3;
    const int ms = (tid & 7) * 8;
    uint2 o[8];
    #pragma unroll
    for (int j = 0; j < 8; j++)
        split2(t[ms + j][2 * kp], t[ms + j][2 * kp + 1], o[j].x, o[j].y);
    uint2* d = dst + (size_t)(k0 / 2 + kp) * M + m0 + ms;
    *(uint4*)(d)     = *(uint4*)&o[0];
    *(uint4*)(d + 2) = *(uint4*)&o[2];
    *(uint4*)(d + 4) = *(uint4*)&o[4];
    *(uint4*)(d + 6) = *(uint4*)&o[6];
}

// ---------------------------------------------------------------------------
// GEMM core: 512 threads, 256(M) x 128(N) tile, BK=16 (8 k-pairs per stage)
// ---------------------------------------------------------------------------
#define RPA 260
#define RPB 132
#define FRAG_COMPUTE(Abuf, Bbuf)                                              \
  do {                                                                        \
    uint32_t ah[4][4], al[4][4], bh[4][2], bl[4][2];                          \
    _Pragma("unroll")                                                         \
    for (int mt = 0; mt < 4; mt++) {                                          \
      int mb = wm * 64 + mt * 16 + gid;                                       \
      uint2 v00 = (Abuf)[tg * RPA + mb];                                      \
      uint2 v01 = (Abuf)[tg * RPA + mb + 8];                                  \
      uint2 v10 = (Abuf)[(tg + 4) * RPA + mb];                                \
      uint2 v11 = (Abuf)[(tg + 4) * RPA + mb + 8];                            \
      ah[mt][0] = v00.x; ah[mt][1] = v01.x;                                   \
      ah[mt][2] = v10.x; ah[mt][3] = v11.x;                                   \
      al[mt][0] = v00.y; al[mt][1] = v01.y;                                   \
      al[mt][2] = v10.y; al[mt][3] = v11.y;                                   \
    }                                                                         \
    _Pragma("unroll")                                                         \
    for (int nt = 0; nt < 4; nt++) {                                          \
      int nb = wn * 32 + nt * 8 + gid;                                        \
      uint2 w0 = (Bbuf)[tg * RPB + nb];                                       \
      uint2 w1 = (Bbuf)[(tg + 4) * RPB + nb];                                 \
      bh[nt][0] = w0.x; bh[nt][1] = w1.x;                                     \
      bl[nt][0] = w0.y; bl[nt][1] = w1.y;                                     \
    }                                                                         \
    _Pragma("unroll")                                                         \
    for (int mt = 0; mt < 4; mt++)                                            \
      _Pragma("unroll")                                                       \
      for (int nt = 0; nt < 4; nt++) {                                        \
        mma16(acc[mt][nt], ah[mt], bh[nt]);                                   \
        mma16(acc[mt][nt], ah[mt], bl[nt]);                                   \
        mma16(acc[mt][nt], al[mt], bh[nt]);                                   \
      }                                                                       \
  } while (0)

#define ACC_INIT                                                              \
    float acc[4][4][4];                                                      \
    _Pragma("unroll")                                                         \
    for (int i = 0; i < 4; i++)                                               \
      _Pragma("unroll")                                                       \
      for (int j = 0; j < 4; j++)                                             \
        _Pragma("unroll")                                                     \
        for (int t = 0; t < 4; t++) acc[i][j][t] = 0.f;

#define WARP_IDS                                                              \
    const int tid = threadIdx.x;                                              \
    const int warp = tid >> 5, lane = tid & 31;                               \
    const int wm = warp & 3, wn = warp >> 2;                                  \
    const int gid = lane >> 2, tg = lane & 3;

#define SMEM_DECL                                                             \
    __shared__ uint2 As[2][8 * RPA];                                          \
    __shared__ uint2 Bs[2][8 * RPB];

// Copy loads for pre-converted tiles
#define LOAD_AB(AT, ldA, BP, ldB, kp0)                                        \
    do {                                                                      \
        const uint2* ap = (AT) + (size_t)((kp0) + arow) * (ldA) + bm + acol;  \
        a0 = *(const uint4*)ap;                                               \
        a1 = *(const uint4*)(ap + 2);                                         \
        b0 = *(const uint4*)((BP) + (size_t)((kp0) + arow) * (ldB)            \
                             + bn + bcol);                                    \
    } while (0)
#define STS_AB(s)                                                             \
    do {                                                                      \
        *(uint4*)&As[s][arow * RPA + acol]     = a0;                          \
        *(uint4*)&As[s][arow * RPA + acol + 2] = a1;                          \
        *(uint4*)&Bs[s][arow * RPB + bcol]     = b0;                          \
    } while (0)

// ---------------------------------------------------------------------------
// Projection: C = A @ W + bias (K=1024). A,B pre-converted. Optional outputs:
// C fp32 [M][1024], Tout transposed pairs [kp][ldT].
// ---------------------------------------------------------------------------
__global__ void __launch_bounds__(512) gemm_proj(
    const uint2* __restrict__ AT, int M,
    const uint2* __restrict__ BP,
    const float* __restrict__ bias,
    float* __restrict__ C, uint2* __restrict__ Tout, int ldT)
{
    SMEM_DECL;
    const int bm = blockIdx.y * 256;
    const int bn = blockIdx.x * 128;
    WARP_IDS;
    const int arow = tid >> 6;
    const int acol = (tid & 63) * 4;
    const int bcol = (tid & 63) * 2;

    ACC_INIT;
    uint4 a0, a1, b0;

    LOAD_AB(AT, M, BP, Hh, 0);
    STS_AB(0);
    __syncthreads();
    int buf = 0;
    for (int kp0 = 0; kp0 < Hh / 2; kp0 += 8) {
        const bool nxt = (kp0 + 8 < Hh / 2);
        if (nxt) LOAD_AB(AT, M, BP, Hh, kp0 + 8);
        FRAG_COMPUTE(As[buf], Bs[buf]);
        if (nxt) STS_AB(buf ^ 1);
        __syncthreads();
        buf ^= 1;
    }

    #pragma unroll
    for (int mt = 0; mt < 4; mt++) {
        int r0 = bm + wm * 64 + mt * 16 + gid;
        #pragma unroll
        for (int nt = 0; nt < 4; nt++) {
            int col = bn + wn * 32 + nt * 8 + 2 * tg;
            float2 bi = *(const float2*)(bias + col);
            float2 o0 = make_float2(fmaf(acc[mt][nt][0], WINV, bi.x),
                                    fmaf(acc[mt][nt][1], WINV, bi.y));
            float2 o1 = make_float2(fmaf(acc[mt][nt][2], WINV, bi.x),
                                    fmaf(acc[mt][nt][3], WINV, bi.y));
            if (C) {
                *(float2*)(C + (size_t)r0 * Hh + col) = o0;
                *(float2*)(C + (size_t)(r0 + 8) * Hh + col) = o1;
            }
            if (Tout) {
                uint2 u;
                split2(o0.x, o0.y, u.x, u.y);
                Tout[(size_t)(col >> 1) * ldT + r0] = u;
                split2(o1.x, o1.y, u.x, u.y);
                Tout[(size_t)(col >> 1) * ldT + r0 + 8] = u;
            }
        }
    }
}

// ---------------------------------------------------------------------------
// Scores: SC[b, s, e] = Q . KE (K=1024). Both operands pre-converted.
// ---------------------------------------------------------------------------
__global__ void __launch_bounds__(512) gemm_scores(
    const uint2* __restrict__ QT, const uint2* __restrict__ KT,
    float* __restrict__ SC)
{
    SMEM_DECL;
    const int b = blockIdx.z;
    const int bm = b * Ss + blockIdx.y * 256;     // row in [0,BS)
    const int bn = b * Ee + blockIdx.x * 128;     // col in [0,BE)
    WARP_IDS;
    const int arow = tid >> 6;
    const int acol = (tid & 63) * 4;
    const int bcol = (tid & 63) * 2;

    ACC_INIT;
    uint4 a0, a1, b0;

    LOAD_AB(QT, BS, KT, BE, 0);
    STS_AB(0);
    __syncthreads();
    int buf = 0;
    for (int kp0 = 0; kp0 < Hh / 2; kp0 += 8) {
        const bool nxt = (kp0 + 8 < Hh / 2);
        if (nxt) LOAD_AB(QT, BS, KT, BE, kp0 + 8);
        FRAG_COMPUTE(As[buf], Bs[buf]);
        if (nxt) STS_AB(buf ^ 1);
        __syncthreads();
        buf ^= 1;
    }

    const int cb = blockIdx.x * 128;
    #pragma unroll
    for (int mt = 0; mt < 4; mt++) {
        int row = bm + wm * 64 + mt * 16 + gid;
        #pragma unroll
        for (int nt = 0; nt < 4; nt++) {
            int col = cb + wn * 32 + nt * 8 + 2 * tg;
            *(float2*)(SC + (size_t)row * 512 + col) =
                make_float2(acc[mt][nt][0], acc[mt][nt][1]);
            *(float2*)(SC + (size_t)(row + 8) * 512 + col) =
                make_float2(acc[mt][nt][2], acc[mt][nt][3]);
        }
    }
}

// ---------------------------------------------------------------------------
// Context: O = P[.,512] @ VE + p0 * VT (K=512). A split in-kernel, B paired.
// ---------------------------------------------------------------------------
__global__ void __launch_bounds__(512) gemm_ctx(
    const float* __restrict__ P, const float* __restrict__ P0,
    const uint2* __restrict__ VP, const float* __restrict__ VT,
    float* __restrict__ O)
{
    SMEM_DECL;
    const int b = blockIdx.z;
    const int bm = b * Ss + blockIdx.y * 256;
    const int bn = blockIdx.x * 128;
    WARP_IDS;
    const int am = tid >> 1;             // 0..255
    const int akc = (tid & 1) * 8;       // k offset 0 or 8
    const int arow = tid >> 6;
    const int bcol = (tid & 63) * 2;

    ACC_INIT;
    float4 pa0, pa1;
    uint4 b0;

#define LOAD_C(kp0)                                                           \
    do {                                                                      \
        const float* ap = P + (size_t)(bm + am) * 512 + 2 * (kp0) + akc;      \
        pa0 = *(const float4*)ap;                                             \
        pa1 = *(const float4*)(ap + 4);                                       \
        b0 = *(const uint4*)(VP + (size_t)(b * (Ee/2) + (kp0) + arow) * Hh    \
                             + bn + bcol);                                    \
    } while (0)
#define STS_C(s)                                                              \
    do {                                                                      \
        uint2 u;                                                              \
        int kr = akc >> 1;                                                    \
        split2(pa0.x, pa0.y, u.x, u.y); As[s][(kr + 0) * RPA + am] = u;       \
        split2(pa0.z, pa0.w, u.x, u.y); As[s][(kr + 1) * RPA + am] = u;       \
        split2(pa1.x, pa1.y, u.x, u.y); As[s][(kr + 2) * RPA + am] = u;       \
        split2(pa1.z, pa1.w, u.x, u.y); As[s][(kr + 3) * RPA + am] = u;       \
        *(uint4*)&Bs[s][arow * RPB + bcol] = b0;                              \
    } while (0)

    LOAD_C(0);
    STS_C(0);
    __syncthreads();
    int buf = 0;
    for (int kp0 = 0; kp0 < Ee / 2; kp0 += 8) {
        const bool nxt = (kp0 + 8 < Ee / 2);
        if (nxt) LOAD_C(kp0 + 8);
        FRAG_COMPUTE(As[buf], Bs[buf]);
        if (nxt) STS_C(buf ^ 1);
        __syncthreads();
        buf ^= 1;
    }
#undef LOAD_C
#undef STS_C

    #pragma unroll
    for (int mt = 0; mt < 4; mt++) {
        int r0 = bm + wm * 64 + mt * 16 + gid;
        int r1 = r0 + 8;
        float p0 = P0[r0];
        float p1 = P0[r1];
        #pragma unroll
        for (int nt = 0; nt < 4; nt++) {
            int col = bn + wn * 32 + nt * 8 + 2 * tg;
            float2 v0 = *(const float2*)(VT + (size_t)r0 * Hh + col);
            float2 v1 = *(const float2*)(VT + (size_t)r1 * Hh + col);
            float2 o0 = make_float2(fmaf(p0, v0.x, acc[mt][nt][0]),
                                    fmaf(p0, v0.y, acc[mt][nt][1]));
            float2 o1 = make_float2(fmaf(p1, v1.x, acc[mt][nt][2]),
                                    fmaf(p1, v1.y, acc[mt][nt][3]));
            *(float2*)(O + (size_t)r0 * Hh + col) = o0;
            *(float2*)(O + (size_t)r1 * Hh + col) = o1;
        }
    }
}

// ---------------------------------------------------------------------------
// Self-dot + softmax
// ---------------------------------------------------------------------------
__global__ void self_dot_kernel(const float* __restrict__ q,
                                const float* __restrict__ kt,
                                float* __restrict__ S0)
{
    int row  = blockIdx.x * 8 + (threadIdx.x >> 5);
    int lane = threadIdx.x & 31;
    const float4* q4 = (const float4*)(q  + (size_t)row * Hh);
    const float4* k4 = (const float4*)(kt + (size_t)row * Hh);
    float sum = 0.f;
    #pragma unroll
    for (int i = lane; i < Hh / 4; i += 32) {
        float4 a = q4[i], b = k4[i];
        sum += a.x * b.x + a.y * b.y + a.z * b.z + a.w * b.w;
    }
    #pragma unroll
    for (int o = 16; o; o >>= 1) sum += __shfl_xor_sync(0xffffffffu, sum, o);
    if (lane == 0) S0[row] = sum;
}

__global__ void softmax_kernel(float* __restrict__ SC, float* __restrict__ S0)
{
    const int row = blockIdx.x;
    float* s = SC + (size_t)row * 512;
    const int tid = threadIdx.x;
    __shared__ float redm[4], reds[4];

    float4 v = ((float4*)s)[tid];
    float s0 = S0[row];
    float lmax = fmaxf(fmaxf(v.x, v.y), fmaxf(v.z, v.w));
    if (tid == 0) lmax = fmaxf(lmax, s0);
    #pragma unroll
    for (int o = 16; o; o >>= 1)
        lmax = fmaxf(lmax, __shfl_xor_sync(0xffffffffu, lmax, o));
    if ((tid & 31) == 0) redm[tid >> 5] = lmax;
    __syncthreads();
    float m = fmaxf(fmaxf(redm[0], redm[1]), fmaxf(redm[2], redm[3]));

    v.x = expf(v.x - m); v.y = expf(v.y - m);
    v.z = expf(v.z - m); v.w = expf(v.w - m);
    float e0 = expf(s0 - m);
    float lsum = v.x + v.y + v.z + v.w + ((tid == 0) ? e0 : 0.f);
    #pragma unroll
    for (int o = 16; o; o >>= 1) lsum += __shfl_xor_sync(0xffffffffu, lsum, o);
    if ((tid & 31) == 0) reds[tid >> 5] = lsum;
    __syncthreads();
    float inv = 1.f / (reds[0] + reds[1] + reds[2] + reds[3]);

    v.x *= inv; v.y *= inv; v.z *= inv; v.w *= inv;
    ((float4*)s)[tid] = v;
    if (tid == 0) S0[row] = e0 * inv;
}

// ---------------------------------------------------------------------------
extern "C" void kernel_launch(void* const* d_in, const int* in_sizes, int n_in,
                              void* d_out, int out_size)
{
    const float* hs  = (const float*)d_in[0];
    const float* ext = (const float*)d_in[1];
    const float* Wq  = (const float*)d_in[2];
    const float* bq  = (const float*)d_in[3];
    const float* Wk  = (const float*)d_in[4];
    const float* bk  = (const float*)d_in[5];
    const float* Wv  = (const float*)d_in[6];
    const float* bv  = (const float*)d_in[7];
    float* out = (float*)d_out;

    float *q, *kt, *vt, *ve, *sc, *s0;
    uint2 *hsT, *exT, *wc, *qT, *keT, *veP;
    cudaGetSymbolAddress((void**)&q,   g_q);
    cudaGetSymbolAddress((void**)&kt,  g_kt);
    cudaGetSymbolAddress((void**)&vt,  g_vt);
    cudaGetSymbolAddress((void**)&ve,  g_ve);
    cudaGetSymbolAddress((void**)&sc,  g_sc);
    cudaGetSymbolAddress((void**)&s0,  g_s0);
    cudaGetSymbolAddress((void**)&hsT, g_hsT);
    cudaGetSymbolAddress((void**)&exT, g_exT);
    cudaGetSymbolAddress((void**)&wc,  g_wc);
    cudaGetSymbolAddress((void**)&qT,  g_qT);
    cudaGetSymbolAddress((void**)&keT, g_keT);
    cudaGetSymbolAddress((void**)&veP, g_veP);

    // Pre-convert inputs
    conv_trans<<<dim3(BS / 64, Hh / 64), 256>>>(hs,  hsT, BS, Hh);
    conv_trans<<<dim3(BE / 64, Hh / 64), 256>>>(ext, exT, BE, Hh);
    conv_pair<<<dim3(1, Hh / 2), 256>>>(Wq, wc,                 Hh, WSCALE);
    conv_pair<<<dim3(1, Hh / 2), 256>>>(Wk, wc + (Hh/2)*Hh,     Hh, WSCALE);
    conv_pair<<<dim3(1, Hh / 2), 256>>>(Wv, wc + 2*(Hh/2)*(size_t)Hh, Hh, WSCALE);

    // Projections (copy-only mainloops)
    gemm_proj<<<dim3(8, BS / 256), 512>>>(hsT, BS, wc,              bq, q,  qT,  BS);
    gemm_proj<<<dim3(8, BS / 256), 512>>>(hsT, BS, wc + (Hh/2)*Hh,  bk, kt, 0,   0);
    gemm_proj<<<dim3(8, BS / 256), 512>>>(hsT, BS, wc + 2*(Hh/2)*(size_t)Hh,
                                          bv, vt, 0, 0);
    gemm_proj<<<dim3(8, BE / 256), 512>>>(exT, BE, wc + (Hh/2)*Hh,  bk, 0,  keT, BE);
    gemm_proj<<<dim3(8, BE / 256), 512>>>(exT, BE, wc + 2*(Hh/2)*(size_t)Hh,
                                          bv, ve, 0, 0);

    // ve -> paired layout for ctx B-side
    conv_pair<<<dim3(1, BE / 2), 256>>>(ve, veP, Hh, 1.0f);

    // Scores
    self_dot_kernel<<<BS / 8, 256>>>(q, kt, s0);
    gemm_scores<<<dim3(4, Ss / 256, Bb), 512>>>(qT, keT, sc);

    // Softmax
    softmax_kernel<<<BS, 128>>>(sc, s0);

    // Context
    gemm_ctx<<<dim3(8, Ss / 256, Bb), 512>>>(sc, s0, veP, vt, out);
}

// round 9
// speedup vs baseline: 1.1607x; 1.1607x over previous
#include <cuda_runtime.h>
#include <cuda_fp16.h>
#include <cstdint>
#include <math.h>

// Problem dims (fixed)
#define Bb 4
#define Ss 2048
#define Ee 512
#define Hh 1024
#define BS (Bb*Ss)
#define BE (Bb*Ee)

// fp32 scratch
__device__ float g_q [BS*Hh];
__device__ float g_kt[BS*Hh];
__device__ float g_vt[BS*Hh];
__device__ float g_ke[BE*Hh];
__device__ float g_ve[BE*Hh];
__device__ float g_sc[(size_t)BS*512];       // raw ext scores
__device__ float g_s0[BS];                   // self score / prob
// (hi,lo) fp16x2 pair scratch
__device__ uint2 g_hsT[(Hh/2)*(size_t)BS];   // hs  [kp][m]
__device__ uint2 g_exT[(Hh/2)*(size_t)BE];   // ext [kp][m]
__device__ uint2 g_wc [3*(Hh/2)*(size_t)Hh]; // Wq,Wk,Wv [kp][n] (x32)
__device__ uint2 g_qT [(Hh/2)*(size_t)BS];   // q   [kp][s]
__device__ uint2 g_keT[(Hh/2)*(size_t)BE];   // ke  [kp][e]
__device__ uint2 g_veP[(BE/2)*(size_t)Hh];   // ve  [ep][h]
__device__ uint2 g_p2 [(size_t)BS*256];      // probs paired [s][ep]

#define WSCALE 32.0f
#define WINV   (1.0f / 32.0f)

// Split two fp32 (consecutive k) into packed fp16x2 hi + lo. low half = x.
__device__ __forceinline__ void split2(float x, float y,
                                       uint32_t &h, uint32_t &l)
{
    asm("cvt.rn.f16x2.f32 %0, %1, %2;" : "=r"(h) : "f"(y), "f"(x));
    __half2 hv = *reinterpret_cast<__half2*>(&h);
    float2 b = __half22float2(hv);
    asm("cvt.rn.f16x2.f32 %0, %1, %2;" : "=r"(l) : "f"(y - b.y), "f"(x - b.x));
}

__device__ __forceinline__ void mma16(float* d, const uint32_t* a,
                                      const uint32_t* b)
{
    asm volatile(
        "mma.sync.aligned.m16n8k16.row.col.f32.f16.f16.f32 "
        "{%0,%1,%2,%3}, {%4,%5,%6,%7}, {%8,%9}, {%0,%1,%2,%3};"
        : "+f"(d[0]), "+f"(d[1]), "+f"(d[2]), "+f"(d[3])
        : "r"(a[0]), "r"(a[1]), "r"(a[2]), "r"(a[3]),
          "r"(b[0]), "r"(b[1]));
}

// ---------------------------------------------------------------------------
// Convert kernels
// ---------------------------------------------------------------------------
// src [K][N] f32 -> dst [K/2][N] uint2 pairs, scaled.
__global__ void conv_pair(const float* __restrict__ src,
                          uint2* __restrict__ dst, int N, float scale)
{
    int kp = blockIdx.y;
    int n0 = (blockIdx.x * 256 + threadIdx.x) * 4;
    if (n0 >= N) return;
    float4 r0 = *(const float4*)(src + (size_t)(2 * kp) * N + n0);
    float4 r1 = *(const float4*)(src + (size_t)(2 * kp + 1) * N + n0);
    uint2 o[4];
    split2(scale * r0.x, scale * r1.x, o[0].x, o[0].y);
    split2(scale * r0.y, scale * r1.y, o[1].x, o[1].y);
    split2(scale * r0.z, scale * r1.z, o[2].x, o[2].y);
    split2(scale * r0.w, scale * r1.w, o[3].x, o[3].y);
    uint2* d = dst + (size_t)kp * N + n0;
    *(uint4*)d       = *(uint4*)&o[0];
    *(uint4*)(d + 2) = *(uint4*)&o[2];
}

// src [M][K] f32 -> dst [K/2][M] uint2 (transpose + split). 64x64 tiles.
__global__ void conv_trans(const float* __restrict__ src,
                           uint2* __restrict__ dst, int M, int K)
{
    __shared__ float t[64][65];
    const int m0 = blockIdx.x * 64;
    const int k0 = blockIdx.y * 64;
    const int tid = threadIdx.x;
    const int mr = tid >> 2;
    const int kc = (tid & 3) * 4;
    #pragma unroll
    for (int i = 0; i < 4; i++) {
        float4 v = *(const float4*)(src + (size_t)(m0 + mr) * K
                                    + k0 + (kc + i) * 4);
        t[mr][(kc + i) * 4 + 0] = v.x;
        t[mr][(kc + i) * 4 + 1] = v.y;
        t[mr][(kc + i) * 4 + 2] = v.z;
        t[mr][(kc + i) * 4 + 3] = v.w;
    }
    __syncthreads();
    const int kp = tid >> 3;
    const int ms = (tid & 7) * 8;
    uint2 o[8];
    #pragma unroll
    for (int j = 0; j < 8; j++)
        split2(t[ms + j][2 * kp], t[ms + j][2 * kp + 1], o[j].x, o[j].y);
    uint2* d = dst + (size_t)(k0 / 2 + kp) * M + m0 + ms;
    *(uint4*)(d)     = *(uint4*)&o[0];
    *(uint4*)(d + 2) = *(uint4*)&o[2];
    *(uint4*)(d + 4) = *(uint4*)&o[4];
    *(uint4*)(d + 6) = *(uint4*)&o[6];
}

// ---------------------------------------------------------------------------
// GEMM core: 256 threads, 128x128 tile, BK=16 (8 k-pairs/stage), copy loops
// ---------------------------------------------------------------------------
#define RP 132
#define TILE_U2 (8 * RP)

#define FRAG_COMPUTE(Abuf, Bbuf)                                              \
  do {                                                                        \
    uint32_t ah[4][4], al[4][4], bh[4][2], bl[4][2];                          \
    _Pragma("unroll")                                                         \
    for (int mt = 0; mt < 4; mt++) {                                          \
      int mb = wm * 64 + mt * 16 + gid;                                       \
      uint2 v00 = (Abuf)[tg * RP + mb];                                       \
      uint2 v01 = (Abuf)[tg * RP + mb + 8];                                   \
      uint2 v10 = (Abuf)[(tg + 4) * RP + mb];                                 \
      uint2 v11 = (Abuf)[(tg + 4) * RP + mb + 8];                             \
      ah[mt][0] = v00.x; ah[mt][1] = v01.x;                                   \
      ah[mt][2] = v10.x; ah[mt][3] = v11.x;                                   \
      al[mt][0] = v00.y; al[mt][1] = v01.y;                                   \
      al[mt][2] = v10.y; al[mt][3] = v11.y;                                   \
    }                                                                         \
    _Pragma("unroll")                                                         \
    for (int nt = 0; nt < 4; nt++) {                                          \
      int nb = wn * 32 + nt * 8 + gid;                                        \
      uint2 w0 = (Bbuf)[tg * RP + nb];                                        \
      uint2 w1 = (Bbuf)[(tg + 4) * RP + nb];                                  \
      bh[nt][0] = w0.x; bh[nt][1] = w1.x;                                     \
      bl[nt][0] = w0.y; bl[nt][1] = w1.y;                                     \
    }                                                                         \
    _Pragma("unroll")                                                         \
    for (int mt = 0; mt < 4; mt++)                                            \
      _Pragma("unroll")                                                       \
      for (int nt = 0; nt < 4; nt++) {                                        \
        mma16(acc[mt][nt], ah[mt], bh[nt]);                                   \
        mma16(acc[mt][nt], ah[mt], bl[nt]);                                   \
        mma16(acc[mt][nt], al[mt], bh[nt]);                                   \
      }                                                                       \
  } while (0)

#define ACC_INIT                                                              \
    float acc[4][4][4];                                                      \
    _Pragma("unroll")                                                         \
    for (int i = 0; i < 4; i++)                                               \
      _Pragma("unroll")                                                       \
      for (int j = 0; j < 4; j++)                                             \
        _Pragma("unroll")                                                     \
        for (int t = 0; t < 4; t++) acc[i][j][t] = 0.f;

#define WARP_IDS                                                              \
    const int tid = threadIdx.x;                                              \
    const int warp = tid >> 5, lane = tid & 31;                               \
    const int wm = warp & 1, wn = warp >> 1;                                  \
    const int gid = lane >> 2, tg = lane & 3;

#define SMEM_DECL                                                             \
    __shared__ uint2 As[2][TILE_U2];                                          \
    __shared__ uint2 Bs[2][TILE_U2];

// Copy loads: both operands pre-paired, [kp][col] layout. 4 uint2/thread each.
#define LOAD_AB(AT, ldA, aoff, BP, ldB, boff, kp0)                            \
    do {                                                                      \
        const uint2* ap = (AT) + (size_t)((kp0) + crow) * (ldA)               \
                          + (aoff) + ccol;                                    \
        a0 = *(const uint4*)ap;                                               \
        a1 = *(const uint4*)(ap + 2);                                         \
        const uint2* bp = (BP) + (size_t)((kp0) + crow) * (ldB)               \
                          + (boff) + ccol;                                    \
        b0 = *(const uint4*)bp;                                               \
        b1 = *(const uint4*)(bp + 2);                                         \
    } while (0)
#define STS_AB(s)                                                             \
    do {                                                                      \
        *(uint4*)&As[s][crow * RP + ccol]     = a0;                           \
        *(uint4*)&As[s][crow * RP + ccol + 2] = a1;                           \
        *(uint4*)&Bs[s][crow * RP + ccol]     = b0;                           \
        *(uint4*)&Bs[s][crow * RP + ccol + 2] = b1;                           \
    } while (0)

// ---------------------------------------------------------------------------
// Projection: C = A @ W + bias (K=1024), fp32 out.
// ---------------------------------------------------------------------------
__global__ void __launch_bounds__(256) gemm_proj(
    const uint2* __restrict__ AT, int ldA,
    const uint2* __restrict__ BP,
    const float* __restrict__ bias, float* __restrict__ C)
{
    SMEM_DECL;
    const int bm = blockIdx.y * 128;
    const int bn = blockIdx.x * 128;
    WARP_IDS;
    const int crow = tid >> 5;
    const int ccol = (tid & 31) * 4;

    ACC_INIT;
    uint4 a0, a1, b0, b1;

    LOAD_AB(AT, ldA, bm, BP, Hh, bn, 0);
    STS_AB(0);
    __syncthreads();
    int buf = 0;
    for (int kp0 = 0; kp0 < Hh / 2; kp0 += 8) {
        const bool nxt = (kp0 + 8 < Hh / 2);
        if (nxt) LOAD_AB(AT, ldA, bm, BP, Hh, bn, kp0 + 8);
        FRAG_COMPUTE(As[buf], Bs[buf]);
        if (nxt) STS_AB(buf ^ 1);
        __syncthreads();
        buf ^= 1;
    }

    #pragma unroll
    for (int mt = 0; mt < 4; mt++) {
        int r0 = bm + wm * 64 + mt * 16 + gid;
        #pragma unroll
        for (int nt = 0; nt < 4; nt++) {
            int col = bn + wn * 32 + nt * 8 + 2 * tg;
            float2 bi = *(const float2*)(bias + col);
            float2 o0 = make_float2(fmaf(acc[mt][nt][0], WINV, bi.x),
                                    fmaf(acc[mt][nt][1], WINV, bi.y));
            float2 o1 = make_float2(fmaf(acc[mt][nt][2], WINV, bi.x),
                                    fmaf(acc[mt][nt][3], WINV, bi.y));
            *(float2*)(C + (size_t)r0 * Hh + col) = o0;
            *(float2*)(C + (size_t)(r0 + 8) * Hh + col) = o1;
        }
    }
}

// ---------------------------------------------------------------------------
// Scores: SC[b, s, e] = Q . KE (K=1024). Both operands pre-paired.
// ---------------------------------------------------------------------------
__global__ void __launch_bounds__(256) gemm_scores(
    const uint2* __restrict__ QT, const uint2* __restrict__ KT,
    float* __restrict__ SC)
{
    SMEM_DECL;
    const int b = blockIdx.z;
    const int bm = b * Ss + blockIdx.y * 128;
    const int bn = b * Ee + blockIdx.x * 128;
    WARP_IDS;
    const int crow = tid >> 5;
    const int ccol = (tid & 31) * 4;

    ACC_INIT;
    uint4 a0, a1, b0, b1;

    LOAD_AB(QT, BS, bm, KT, BE, bn, 0);
    STS_AB(0);
    __syncthreads();
    int buf = 0;
    for (int kp0 = 0; kp0 < Hh / 2; kp0 += 8) {
        const bool nxt = (kp0 + 8 < Hh / 2);
        if (nxt) LOAD_AB(QT, BS, bm, KT, BE, bn, kp0 + 8);
        FRAG_COMPUTE(As[buf], Bs[buf]);
        if (nxt) STS_AB(buf ^ 1);
        __syncthreads();
        buf ^= 1;
    }

    const int cb = blockIdx.x * 128;
    #pragma unroll
    for (int mt = 0; mt < 4; mt++) {
        int row = bm + wm * 64 + mt * 16 + gid;
        #pragma unroll
        for (int nt = 0; nt < 4; nt++) {
            int col = cb + wn * 32 + nt * 8 + 2 * tg;
            *(float2*)(SC + (size_t)row * 512 + col) =
                make_float2(acc[mt][nt][0], acc[mt][nt][1]);
            *(float2*)(SC + (size_t)(row + 8) * 512 + col) =
                make_float2(acc[mt][nt][2], acc[mt][nt][3]);
        }
    }
}

// ---------------------------------------------------------------------------
// Context: O = P2 @ VE + p0 * VT (K=512). P2 paired row-major, VE paired.
// ---------------------------------------------------------------------------
__global__ void __launch_bounds__(256) gemm_ctx(
    const uint2* __restrict__ P2, const float* __restrict__ P0,
    const uint2* __restrict__ VP, const float* __restrict__ VT,
    float* __restrict__ O)
{
    SMEM_DECL;
    const int b = blockIdx.z;
    const int bm = b * Ss + blockIdx.y * 128;
    const int bn = blockIdx.x * 128;
    WARP_IDS;
    const int am  = tid & 127;          // A: m row
    const int akp = (tid >> 7) * 4;     // A: kp offset 0 or 4
    const int crow = tid >> 5;
    const int ccol = (tid & 31) * 4;

    ACC_INIT;
    uint4 u0, u1, b0, b1;

#define LOAD_C(kp0)                                                           \
    do {                                                                      \
        const uint2* pp = P2 + (size_t)(bm + am) * 256 + (kp0) + akp;         \
        u0 = *(const uint4*)pp;                                               \
        u1 = *(const uint4*)(pp + 2);                                         \
        const uint2* bp = VP + (size_t)(b * (Ee/2) + (kp0) + crow) * Hh       \
                          + bn + ccol;                                        \
        b0 = *(const uint4*)bp;                                               \
        b1 = *(const uint4*)(bp + 2);                                         \
    } while (0)
#define STS_C(s)                                                              \
    do {                                                                      \
        As[s][(akp + 0) * RP + am] = make_uint2(u0.x, u0.y);                  \
        As[s][(akp + 1) * RP + am] = make_uint2(u0.z, u0.w);                  \
        As[s][(akp + 2) * RP + am] = make_uint2(u1.x, u1.y);                  \
        As[s][(akp + 3) * RP + am] = make_uint2(u1.z, u1.w);                  \
        *(uint4*)&Bs[s][crow * RP + ccol]     = b0;                           \
        *(uint4*)&Bs[s][crow * RP + ccol + 2] = b1;                           \
    } while (0)

    LOAD_C(0);
    STS_C(0);
    __syncthreads();
    int buf = 0;
    for (int kp0 = 0; kp0 < Ee / 2; kp0 += 8) {
        const bool nxt = (kp0 + 8 < Ee / 2);
        if (nxt) LOAD_C(kp0 + 8);
        FRAG_COMPUTE(As[buf], Bs[buf]);
        if (nxt) STS_C(buf ^ 1);
        __syncthreads();
        buf ^= 1;
    }
#undef LOAD_C
#undef STS_C

    #pragma unroll
    for (int mt = 0; mt < 4; mt++) {
        int r0 = bm + wm * 64 + mt * 16 + gid;
        int r1 = r0 + 8;
        float p0 = P0[r0];
        float p1 = P0[r1];
        #pragma unroll
        for (int nt = 0; nt < 4; nt++) {
            int col = bn + wn * 32 + nt * 8 + 2 * tg;
            float2 v0 = *(const float2*)(VT + (size_t)r0 * Hh + col);
            float2 v1 = *(const float2*)(VT + (size_t)r1 * Hh + col);
            float2 o0 = make_float2(fmaf(p0, v0.x, acc[mt][nt][0]),
                                    fmaf(p0, v0.y, acc[mt][nt][1]));
            float2 o1 = make_float2(fmaf(p1, v1.x, acc[mt][nt][2]),
                                    fmaf(p1, v1.y, acc[mt][nt][3]));
            *(float2*)(O + (size_t)r0 * Hh + col) = o0;
            *(float2*)(O + (size_t)r1 * Hh + col) = o1;
        }
    }
}

// ---------------------------------------------------------------------------
// Self-dot + softmax (softmax emits paired probs for ctx)
// ---------------------------------------------------------------------------
__global__ void self_dot_kernel(const float* __restrict__ q,
                                const float* __restrict__ kt,
                                float* __restrict__ S0)
{
    int row  = blockIdx.x * 8 + (threadIdx.x >> 5);
    int lane = threadIdx.x & 31;
    const float4* q4 = (const float4*)(q  + (size_t)row * Hh);
    const float4* k4 = (const float4*)(kt + (size_t)row * Hh);
    float sum = 0.f;
    #pragma unroll
    for (int i = lane; i < Hh / 4; i += 32) {
        float4 a = q4[i], b = k4[i];
        sum += a.x * b.x + a.y * b.y + a.z * b.z + a.w * b.w;
    }
    #pragma unroll
    for (int o = 16; o; o >>= 1) sum += __shfl_xor_sync(0xffffffffu, sum, o);
    if (lane == 0) S0[row] = sum;
}

__global__ void softmax_kernel(const float* __restrict__ SC,
                               float* __restrict__ S0,
                               uint2* __restrict__ P2)
{
    const int row = blockIdx.x;
    const float* s = SC + (size_t)row * 512;
    const int tid = threadIdx.x;
    __shared__ float redm[4], reds[4];

    float4 v = ((const float4*)s)[tid];
    float s0 = S0[row];
    float lmax = fmaxf(fmaxf(v.x, v.y), fmaxf(v.z, v.w));
    if (tid == 0) lmax = fmaxf(lmax, s0);
    #pragma unroll
    for (int o = 16; o; o >>= 1)
        lmax = fmaxf(lmax, __shfl_xor_sync(0xffffffffu, lmax, o));
    if ((tid & 31) == 0) redm[tid >> 5] = lmax;
    __syncthreads();
    float m = fmaxf(fmaxf(redm[0], redm[1]), fmaxf(redm[2], redm[3]));

    v.x = expf(v.x - m); v.y = expf(v.y - m);
    v.z = expf(v.z - m); v.w = expf(v.w - m);
    float e0 = expf(s0 - m);
    float lsum = v.x + v.y + v.z + v.w + ((tid == 0) ? e0 : 0.f);
    #pragma unroll
    for (int o = 16; o; o >>= 1) lsum += __shfl_xor_sync(0xffffffffu, lsum, o);
    if ((tid & 31) == 0) reds[tid >> 5] = lsum;
    __syncthreads();
    float inv = 1.f / (reds[0] + reds[1] + reds[2] + reds[3]);

    uint2 o0, o1;
    split2(v.x * inv, v.y * inv, o0.x, o0.y);
    split2(v.z * inv, v.w * inv, o1.x, o1.y);
    uint2* d = P2 + (size_t)row * 256 + tid * 2;
    d[0] = o0;
    d[1] = o1;
    if (tid == 0) S0[row] = e0 * inv;
}

// ---------------------------------------------------------------------------
extern "C" void kernel_launch(void* const* d_in, const int* in_sizes, int n_in,
                              void* d_out, int out_size)
{
    const float* hs  = (const float*)d_in[0];
    const float* ext = (const float*)d_in[1];
    const float* Wq  = (const float*)d_in[2];
    const float* bq  = (const float*)d_in[3];
    const float* Wk  = (const float*)d_in[4];
    const float* bk  = (const float*)d_in[5];
    const float* Wv  = (const float*)d_in[6];
    const float* bv  = (const float*)d_in[7];
    float* out = (float*)d_out;

    float *q, *kt, *vt, *ke, *ve, *sc, *s0;
    uint2 *hsT, *exT, *wc, *qT, *keT, *veP, *p2;
    cudaGetSymbolAddress((void**)&q,   g_q);
    cudaGetSymbolAddress((void**)&kt,  g_kt);
    cudaGetSymbolAddress((void**)&vt,  g_vt);
    cudaGetSymbolAddress((void**)&ke,  g_ke);
    cudaGetSymbolAddress((void**)&ve,  g_ve);
    cudaGetSymbolAddress((void**)&sc,  g_sc);
    cudaGetSymbolAddress((void**)&s0,  g_s0);
    cudaGetSymbolAddress((void**)&hsT, g_hsT);
    cudaGetSymbolAddress((void**)&exT, g_exT);
    cudaGetSymbolAddress((void**)&wc,  g_wc);
    cudaGetSymbolAddress((void**)&qT,  g_qT);
    cudaGetSymbolAddress((void**)&keT, g_keT);
    cudaGetSymbolAddress((void**)&veP, g_veP);
    cudaGetSymbolAddress((void**)&p2,  g_p2);

    const size_t WOFF = (size_t)(Hh / 2) * Hh;

    // Pre-convert inputs
    conv_trans<<<dim3(BS / 64, Hh / 64), 256>>>(hs,  hsT, BS, Hh);
    conv_trans<<<dim3(BE / 64, Hh / 64), 256>>>(ext, exT, BE, Hh);
    conv_pair<<<dim3(1, Hh / 2), 256>>>(Wq, wc,            Hh, WSCALE);
    conv_pair<<<dim3(1, Hh / 2), 256>>>(Wk, wc + WOFF,     Hh, WSCALE);
    conv_pair<<<dim3(1, Hh / 2), 256>>>(Wv, wc + 2 * WOFF, Hh, WSCALE);

    // Projections (pure copy mainloops)
    gemm_proj<<<dim3(8, BS / 128), 256>>>(hsT, BS, wc,            bq, q);
    gemm_proj<<<dim3(8, BS / 128), 256>>>(hsT, BS, wc + WOFF,     bk, kt);
    gemm_proj<<<dim3(8, BS / 128), 256>>>(hsT, BS, wc + 2 * WOFF, bv, vt);
    gemm_proj<<<dim3(8, BE / 128), 256>>>(exT, BE, wc + WOFF,     bk, ke);
    gemm_proj<<<dim3(8, BE / 128), 256>>>(exT, BE, wc + 2 * WOFF, bv, ve);

    // Convert activations for scores / ctx
    conv_trans<<<dim3(BS / 64, Hh / 64), 256>>>(q,  qT,  BS, Hh);
    conv_trans<<<dim3(BE / 64, Hh / 64), 256>>>(ke, keT, BE, Hh);
    conv_pair<<<dim3(1, BE / 2), 256>>>(ve, veP, Hh, 1.0f);

    // Scores
    self_dot_kernel<<<BS / 8, 256>>>(q, kt, s0);
    gemm_scores<<<dim3(4, Ss / 128, Bb), 256>>>(qT, keT, sc);

    // Softmax (emits paired probs)
    softmax_kernel<<<BS, 128>>>(sc, s0, p2);

    // Context
    gemm_ctx<<<dim3(8, Ss / 128, Bb), 256>>>(p2, s0, veP, vt, out);
}

// round 10
// speedup vs baseline: 1.1690x; 1.0072x over previous
#include <cuda_runtime.h>
#include <cuda_fp16.h>
#include <cstdint>
#include <math.h>

// Problem dims (fixed)
#define Bb 4
#define Ss 2048
#define Ee 512
#define Hh 1024
#define BS (Bb*Ss)
#define BE (Bb*Ee)

// fp32 scratch
__device__ float g_q [BS*Hh];
__device__ float g_kt[BS*Hh];
__device__ float g_vt[BS*Hh];
__device__ float g_ke[BE*Hh];
__device__ float g_ve[BE*Hh];
__device__ float g_sc[(size_t)BS*512];       // raw ext scores
__device__ float g_s0[BS];                   // self score / prob
// (hi,lo) fp16x2 pair scratch (16B aligned for cp.async)
__device__ __align__(16) uint2 g_hsT[(Hh/2)*(size_t)BS];
__device__ __align__(16) uint2 g_exT[(Hh/2)*(size_t)BE];
__device__ __align__(16) uint2 g_wc [3*(Hh/2)*(size_t)Hh];
__device__ __align__(16) uint2 g_qT [(Hh/2)*(size_t)BS];
__device__ __align__(16) uint2 g_keT[(Hh/2)*(size_t)BE];
__device__ __align__(16) uint2 g_veP[(BE/2)*(size_t)Hh];
__device__ __align__(16) uint2 g_p2 [(size_t)BS*256];

#define WSCALE 32.0f
#define WINV   (1.0f / 32.0f)

// Split two fp32 (consecutive k) into packed fp16x2 hi + lo. low half = x.
__device__ __forceinline__ void split2(float x, float y,
                                       uint32_t &h, uint32_t &l)
{
    asm("cvt.rn.f16x2.f32 %0, %1, %2;" : "=r"(h) : "f"(y), "f"(x));
    __half2 hv = *reinterpret_cast<__half2*>(&h);
    float2 b = __half22float2(hv);
    asm("cvt.rn.f16x2.f32 %0, %1, %2;" : "=r"(l) : "f"(y - b.y), "f"(x - b.x));
}

__device__ __forceinline__ void mma16(float* d, const uint32_t* a,
                                      const uint32_t* b)
{
    asm volatile(
        "mma.sync.aligned.m16n8k16.row.col.f32.f16.f16.f32 "
        "{%0,%1,%2,%3}, {%4,%5,%6,%7}, {%8,%9}, {%0,%1,%2,%3};"
        : "+f"(d[0]), "+f"(d[1]), "+f"(d[2]), "+f"(d[3])
        : "r"(a[0]), "r"(a[1]), "r"(a[2]), "r"(a[3]),
          "r"(b[0]), "r"(b[1]));
}

__device__ __forceinline__ void cpa(uint32_t d, const void* s)
{
    asm volatile("cp.async.cg.shared.global [%0], [%1], 16;"
                 :: "r"(d), "l"(s) : "memory");
}
#define CP_COMMIT() asm volatile("cp.async.commit_group;" ::: "memory")
#define CP_WAIT2()  asm volatile("cp.async.wait_group 2;" ::: "memory")

// ---------------------------------------------------------------------------
// Convert kernels
// ---------------------------------------------------------------------------
__global__ void conv_pair(const float* __restrict__ src,
                          uint2* __restrict__ dst, int N, float scale)
{
    int kp = blockIdx.y;
    int n0 = (blockIdx.x * 256 + threadIdx.x) * 4;
    if (n0 >= N) return;
    float4 r0 = *(const float4*)(src + (size_t)(2 * kp) * N + n0);
    float4 r1 = *(const float4*)(src + (size_t)(2 * kp + 1) * N + n0);
    uint2 o[4];
    split2(scale * r0.x, scale * r1.x, o[0].x, o[0].y);
    split2(scale * r0.y, scale * r1.y, o[1].x, o[1].y);
    split2(scale * r0.z, scale * r1.z, o[2].x, o[2].y);
    split2(scale * r0.w, scale * r1.w, o[3].x, o[3].y);
    uint2* d = dst + (size_t)kp * N + n0;
    *(uint4*)d       = *(uint4*)&o[0];
    *(uint4*)(d + 2) = *(uint4*)&o[2];
}

__global__ void conv_trans(const float* __restrict__ src,
                           uint2* __restrict__ dst, int M, int K)
{
    __shared__ float t[64][65];
    const int m0 = blockIdx.x * 64;
    const int k0 = blockIdx.y * 64;
    const int tid = threadIdx.x;
    const int mr = tid >> 2;
    const int kc = (tid & 3) * 4;
    #pragma unroll
    for (int i = 0; i < 4; i++) {
        float4 v = *(const float4*)(src + (size_t)(m0 + mr) * K
                                    + k0 + (kc + i) * 4);
        t[mr][(kc + i) * 4 + 0] = v.x;
        t[mr][(kc + i) * 4 + 1] = v.y;
        t[mr][(kc + i) * 4 + 2] = v.z;
        t[mr][(kc + i) * 4 + 3] = v.w;
    }
    __syncthreads();
    const int kp = tid >> 3;
    const int ms = (tid & 7) * 8;
    uint2 o[8];
    #pragma unroll
    for (int j = 0; j < 8; j++)
        split2(t[ms + j][2 * kp], t[ms + j][2 * kp + 1], o[j].x, o[j].y);
    uint2* d = dst + (size_t)(k0 / 2 + kp) * M + m0 + ms;
    *(uint4*)(d)     = *(uint4*)&o[0];
    *(uint4*)(d + 2) = *(uint4*)&o[2];
    *(uint4*)(d + 4) = *(uint4*)&o[4];
    *(uint4*)(d + 6) = *(uint4*)&o[6];
}

// ---------------------------------------------------------------------------
// GEMM core pieces: 256 threads, 128x128 tile, BK=16 (8 kp/stage)
// ---------------------------------------------------------------------------
#define RP 132
#define STG_U2 (8 * RP)
#define STAGES 4
#define SMEM_GEMM (STAGES * STG_U2 * 2 * 8)   // 67584 B

#define FRAG_COMPUTE(Abuf, Bbuf)                                              \
  do {                                                                        \
    uint32_t ah[4][4], al[4][4], bh[4][2], bl[4][2];                          \
    _Pragma("unroll")                                                         \
    for (int mt = 0; mt < 4; mt++) {                                          \
      int mb = wm * 64 + mt * 16 + gid;                                       \
      uint2 v00 = (Abuf)[tg * RP + mb];                                       \
      uint2 v01 = (Abuf)[tg * RP + mb + 8];                                   \
      uint2 v10 = (Abuf)[(tg + 4) * RP + mb];                                 \
      uint2 v11 = (Abuf)[(tg + 4) * RP + mb + 8];                             \
      ah[mt][0] = v00.x; ah[mt][1] = v01.x;                                   \
      ah[mt][2] = v10.x; ah[mt][3] = v11.x;                                   \
      al[mt][0] = v00.y; al[mt][1] = v01.y;                                   \
      al[mt][2] = v10.y; al[mt][3] = v11.y;                                   \
    }                                                                         \
    _Pragma("unroll")                                                         \
    for (int nt = 0; nt < 4; nt++) {                                          \
      int nb = wn * 32 + nt * 8 + gid;                                        \
      uint2 w0 = (Bbuf)[tg * RP + nb];                                        \
      uint2 w1 = (Bbuf)[(tg + 4) * RP + nb];                                  \
      bh[nt][0] = w0.x; bh[nt][1] = w1.x;                                     \
      bl[nt][0] = w0.y; bl[nt][1] = w1.y;                                     \
    }                                                                         \
    _Pragma("unroll")                                                         \
    for (int mt = 0; mt < 4; mt++)                                            \
      _Pragma("unroll")                                                       \
      for (int nt = 0; nt < 4; nt++) {                                        \
        mma16(acc[mt][nt], ah[mt], bh[nt]);                                   \
        mma16(acc[mt][nt], ah[mt], bl[nt]);                                   \
        mma16(acc[mt][nt], al[mt], bh[nt]);                                   \
      }                                                                       \
  } while (0)

#define ACC_INIT                                                              \
    float acc[4][4][4];                                                      \
    _Pragma("unroll")                                                         \
    for (int i = 0; i < 4; i++)                                               \
      _Pragma("unroll")                                                       \
      for (int j = 0; j < 4; j++)                                             \
        _Pragma("unroll")                                                     \
        for (int t = 0; t < 4; t++) acc[i][j][t] = 0.f;

#define WARP_IDS                                                              \
    const int tid = threadIdx.x;                                              \
    const int warp = tid >> 5, lane = tid & 31;                               \
    const int wm = warp & 1, wn = warp >> 1;                                  \
    const int gid = lane >> 2, tg = lane & 3;

// Dynamic smem + shared-address bases for cp.async pipelines
#define PIPE_SMEM                                                             \
    extern __shared__ uint2 dsm[];                                            \
    uint2* const Asm = dsm;                                                   \
    uint2* const Bsm = dsm + STAGES * STG_U2;                                 \
    uint32_t smb;                                                             \
    asm("{ .reg .u64 t; cvta.to.shared.u64 t, %1; cvt.u32.u64 %0, t; }"       \
        : "=r"(smb) : "l"(dsm));                                              \
    const uint32_t sA = smb;                                                  \
    const uint32_t sB = smb + STAGES * STG_U2 * 8;

// Issue one stage: A and B 16B async copies (2 each per thread)
#define ISSUE_AB(s, kp0)                                                      \
    do {                                                                      \
        const uint2* ap_ = Abase + (size_t)((kp0) + crow) * ldA + ccol;       \
        uint32_t da_ = sA + ((s) * STG_U2 + crow * RP + ccol) * 8;            \
        cpa(da_, ap_);                                                        \
        cpa(da_ + 16, ap_ + 2);                                               \
        const uint2* bp_ = Bbase + (size_t)((kp0) + crow) * ldB + ccol;       \
        uint32_t db_ = sB + ((s) * STG_U2 + crow * RP + ccol) * 8;            \
        cpa(db_, bp_);                                                        \
        cpa(db_ + 16, bp_ + 2);                                               \
    } while (0)

#define PIPE_MAINLOOP(NST)                                                    \
    ISSUE_AB(0, 0); CP_COMMIT();                                              \
    ISSUE_AB(1, 8); CP_COMMIT();                                              \
    ISSUE_AB(2, 16); CP_COMMIT();                                             \
    for (int i = 0; i < (NST); i++) {                                         \
        CP_WAIT2();                                                           \
        __syncthreads();                                                      \
        int buf = i & 3;                                                      \
        FRAG_COMPUTE((Asm + buf * STG_U2), (Bsm + buf * STG_U2));             \
        if (i + 3 < (NST)) ISSUE_AB((i + 3) & 3, (i + 3) * 8);                \
        CP_COMMIT();                                                          \
        __syncthreads();                                                      \
    }

// ---------------------------------------------------------------------------
// Projection: C = A @ W + bias (K=1024), cp.async pipeline.
// ---------------------------------------------------------------------------
__global__ void __launch_bounds__(256, 2) gemm_proj(
    const uint2* __restrict__ AT, int ldA,
    const uint2* __restrict__ BP,
    const float* __restrict__ bias, float* __restrict__ C)
{
    PIPE_SMEM;
    const int bm = blockIdx.y * 128;
    const int bn = blockIdx.x * 128;
    WARP_IDS;
    const int crow = tid >> 5;
    const int ccol = (tid & 31) * 4;
    const uint2* Abase = AT + bm;
    const uint2* Bbase = BP + bn;
    const int ldB = Hh;

    ACC_INIT;
    PIPE_MAINLOOP(Hh / 16);

    #pragma unroll
    for (int mt = 0; mt < 4; mt++) {
        int r0 = bm + wm * 64 + mt * 16 + gid;
        #pragma unroll
        for (int nt = 0; nt < 4; nt++) {
            int col = bn + wn * 32 + nt * 8 + 2 * tg;
            float2 bi = *(const float2*)(bias + col);
            float2 o0 = make_float2(fmaf(acc[mt][nt][0], WINV, bi.x),
                                    fmaf(acc[mt][nt][1], WINV, bi.y));
            float2 o1 = make_float2(fmaf(acc[mt][nt][2], WINV, bi.x),
                                    fmaf(acc[mt][nt][3], WINV, bi.y));
            *(float2*)(C + (size_t)r0 * Hh + col) = o0;
            *(float2*)(C + (size_t)(r0 + 8) * Hh + col) = o1;
        }
    }
}

// ---------------------------------------------------------------------------
// Scores: SC[b, s, e] = Q . KE (K=1024), cp.async pipeline.
// ---------------------------------------------------------------------------
__global__ void __launch_bounds__(256, 2) gemm_scores(
    const uint2* __restrict__ QT, const uint2* __restrict__ KT,
    float* __restrict__ SC)
{
    PIPE_SMEM;
    const int b = blockIdx.z;
    const int bm = b * Ss + blockIdx.y * 128;
    const int bn = b * Ee + blockIdx.x * 128;
    WARP_IDS;
    const int crow = tid >> 5;
    const int ccol = (tid & 31) * 4;
    const uint2* Abase = QT + bm;
    const uint2* Bbase = KT + bn;
    const int ldA = BS, ldB = BE;

    ACC_INIT;
    PIPE_MAINLOOP(Hh / 16);

    const int cb = blockIdx.x * 128;
    #pragma unroll
    for (int mt = 0; mt < 4; mt++) {
        int row = bm + wm * 64 + mt * 16 + gid;
        #pragma unroll
        for (int nt = 0; nt < 4; nt++) {
            int col = cb + wn * 32 + nt * 8 + 2 * tg;
            *(float2*)(SC + (size_t)row * 512 + col) =
                make_float2(acc[mt][nt][0], acc[mt][nt][1]);
            *(float2*)(SC + (size_t)(row + 8) * 512 + col) =
                make_float2(acc[mt][nt][2], acc[mt][nt][3]);
        }
    }
}

// ---------------------------------------------------------------------------
// Context: O = P2 @ VE + p0 * VT (K=512). Round-9 double-buffer version.
// ---------------------------------------------------------------------------
__global__ void __launch_bounds__(256) gemm_ctx(
    const uint2* __restrict__ P2, const float* __restrict__ P0,
    const uint2* __restrict__ VP, const float* __restrict__ VT,
    float* __restrict__ O)
{
    __shared__ uint2 As[2][STG_U2];
    __shared__ uint2 Bs[2][STG_U2];
    const int b = blockIdx.z;
    const int bm = b * Ss + blockIdx.y * 128;
    const int bn = blockIdx.x * 128;
    WARP_IDS;
    const int am  = tid & 127;
    const int akp = (tid >> 7) * 4;
    const int crow = tid >> 5;
    const int ccol = (tid & 31) * 4;

    ACC_INIT;
    uint4 u0, u1, b0, b1;

#define LOAD_C(kp0)                                                           \
    do {                                                                      \
        const uint2* pp = P2 + (size_t)(bm + am) * 256 + (kp0) + akp;         \
        u0 = *(const uint4*)pp;                                               \
        u1 = *(const uint4*)(pp + 2);                                         \
        const uint2* bp = VP + (size_t)(b * (Ee/2) + (kp0) + crow) * Hh       \
                          + bn + ccol;                                        \
        b0 = *(const uint4*)bp;                                               \
        b1 = *(const uint4*)(bp + 2);                                         \
    } while (0)
#define STS_C(s)                                                              \
    do {                                                                      \
        As[s][(akp + 0) * RP + am] = make_uint2(u0.x, u0.y);                  \
        As[s][(akp + 1) * RP + am] = make_uint2(u0.z, u0.w);                  \
        As[s][(akp + 2) * RP + am] = make_uint2(u1.x, u1.y);                  \
        As[s][(akp + 3) * RP + am] = make_uint2(u1.z, u1.w);                  \
        *(uint4*)&Bs[s][crow * RP + ccol]     = b0;                           \
        *(uint4*)&Bs[s][crow * RP + ccol + 2] = b1;                           \
    } while (0)

    LOAD_C(0);
    STS_C(0);
    __syncthreads();
    int buf = 0;
    for (int kp0 = 0; kp0 < Ee / 2; kp0 += 8) {
        const bool nxt = (kp0 + 8 < Ee / 2);
        if (nxt) LOAD_C(kp0 + 8);
        FRAG_COMPUTE(As[buf], Bs[buf]);
        if (nxt) STS_C(buf ^ 1);
        __syncthreads();
        buf ^= 1;
    }
#undef LOAD_C
#undef STS_C

    #pragma unroll
    for (int mt = 0; mt < 4; mt++) {
        int r0 = bm + wm * 64 + mt * 16 + gid;
        int r1 = r0 + 8;
        float p0 = P0[r0];
        float p1 = P0[r1];
        #pragma unroll
        for (int nt = 0; nt < 4; nt++) {
            int col = bn + wn * 32 + nt * 8 + 2 * tg;
            float2 v0 = *(const float2*)(VT + (size_t)r0 * Hh + col);
            float2 v1 = *(const float2*)(VT + (size_t)r1 * Hh + col);
            float2 o0 = make_float2(fmaf(p0, v0.x, acc[mt][nt][0]),
                                    fmaf(p0, v0.y, acc[mt][nt][1]));
            float2 o1 = make_float2(fmaf(p1, v1.x, acc[mt][nt][2]),
                                    fmaf(p1, v1.y, acc[mt][nt][3]));
            *(float2*)(O + (size_t)r0 * Hh + col) = o0;
            *(float2*)(O + (size_t)r1 * Hh + col) = o1;
        }
    }
}

// ---------------------------------------------------------------------------
// Self-dot + softmax
// ---------------------------------------------------------------------------
__global__ void self_dot_kernel(const float* __restrict__ q,
                                const float* __restrict__ kt,
                                float* __restrict__ S0)
{
    int row  = blockIdx.x * 8 + (threadIdx.x >> 5);
    int lane = threadIdx.x & 31;
    const float4* q4 = (const float4*)(q  + (size_t)row * Hh);
    const float4* k4 = (const float4*)(kt + (size_t)row * Hh);
    float sum = 0.f;
    #pragma unroll
    for (int i = lane; i < Hh / 4; i += 32) {
        float4 a = q4[i], b = k4[i];
        sum += a.x * b.x + a.y * b.y + a.z * b.z + a.w * b.w;
    }
    #pragma unroll
    for (int o = 16; o; o >>= 1) sum += __shfl_xor_sync(0xffffffffu, sum, o);
    if (lane == 0) S0[row] = sum;
}

__global__ void softmax_kernel(const float* __restrict__ SC,
                               float* __restrict__ S0,
                               uint2* __restrict__ P2)
{
    const int row = blockIdx.x;
    const float* s = SC + (size_t)row * 512;
    const int tid = threadIdx.x;
    __shared__ float redm[4], reds[4];

    float4 v = ((const float4*)s)[tid];
    float s0 = S0[row];
    float lmax = fmaxf(fmaxf(v.x, v.y), fmaxf(v.z, v.w));
    if (tid == 0) lmax = fmaxf(lmax, s0);
    #pragma unroll
    for (int o = 16; o; o >>= 1)
        lmax = fmaxf(lmax, __shfl_xor_sync(0xffffffffu, lmax, o));
    if ((tid & 31) == 0) redm[tid >> 5] = lmax;
    __syncthreads();
    float m = fmaxf(fmaxf(redm[0], redm[1]), fmaxf(redm[2], redm[3]));

    v.x = expf(v.x - m); v.y = expf(v.y - m);
    v.z = expf(v.z - m); v.w = expf(v.w - m);
    float e0 = expf(s0 - m);
    float lsum = v.x + v.y + v.z + v.w + ((tid == 0) ? e0 : 0.f);
    #pragma unroll
    for (int o = 16; o; o >>= 1) lsum += __shfl_xor_sync(0xffffffffu, lsum, o);
    if ((tid & 31) == 0) reds[tid >> 5] = lsum;
    __syncthreads();
    float inv = 1.f / (reds[0] + reds[1] + reds[2] + reds[3]);

    uint2 o0, o1;
    split2(v.x * inv, v.y * inv, o0.x, o0.y);
    split2(v.z * inv, v.w * inv, o1.x, o1.y);
    uint2* d = P2 + (size_t)row * 256 + tid * 2;
    d[0] = o0;
    d[1] = o1;
    if (tid == 0) S0[row] = e0 * inv;
}

// ---------------------------------------------------------------------------
extern "C" void kernel_launch(void* const* d_in, const int* in_sizes, int n_in,
                              void* d_out, int out_size)
{
    const float* hs  = (const float*)d_in[0];
    const float* ext = (const float*)d_in[1];
    const float* Wq  = (const float*)d_in[2];
    const float* bq  = (const float*)d_in[3];
    const float* Wk  = (const float*)d_in[4];
    const float* bk  = (const float*)d_in[5];
    const float* Wv  = (const float*)d_in[6];
    const float* bv  = (const float*)d_in[7];
    float* out = (float*)d_out;

    float *q, *kt, *vt, *ke, *ve, *sc, *s0;
    uint2 *hsT, *exT, *wc, *qT, *keT, *veP, *p2;
    cudaGetSymbolAddress((void**)&q,   g_q);
    cudaGetSymbolAddress((void**)&kt,  g_kt);
    cudaGetSymbolAddress((void**)&vt,  g_vt);
    cudaGetSymbolAddress((void**)&ke,  g_ke);
    cudaGetSymbolAddress((void**)&ve,  g_ve);
    cudaGetSymbolAddress((void**)&sc,  g_sc);
    cudaGetSymbolAddress((void**)&s0,  g_s0);
    cudaGetSymbolAddress((void**)&hsT, g_hsT);
    cudaGetSymbolAddress((void**)&exT, g_exT);
    cudaGetSymbolAddress((void**)&wc,  g_wc);
    cudaGetSymbolAddress((void**)&qT,  g_qT);
    cudaGetSymbolAddress((void**)&keT, g_keT);
    cudaGetSymbolAddress((void**)&veP, g_veP);
    cudaGetSymbolAddress((void**)&p2,  g_p2);

    const size_t WOFF = (size_t)(Hh / 2) * Hh;

    cudaFuncSetAttribute(gemm_proj,
        cudaFuncAttributeMaxDynamicSharedMemorySize, SMEM_GEMM);
    cudaFuncSetAttribute(gemm_scores,
        cudaFuncAttributeMaxDynamicSharedMemorySize, SMEM_GEMM);

    // Pre-convert inputs
    conv_trans<<<dim3(BS / 64, Hh / 64), 256>>>(hs,  hsT, BS, Hh);
    conv_trans<<<dim3(BE / 64, Hh / 64), 256>>>(ext, exT, BE, Hh);
    conv_pair<<<dim3(1, Hh / 2), 256>>>(Wq, wc,            Hh, WSCALE);
    conv_pair<<<dim3(1, Hh / 2), 256>>>(Wk, wc + WOFF,     Hh, WSCALE);
    conv_pair<<<dim3(1, Hh / 2), 256>>>(Wv, wc + 2 * WOFF, Hh, WSCALE);

    // Projections (cp.async pipelined mainloops)
    gemm_proj<<<dim3(8, BS / 128), 256, SMEM_GEMM>>>(hsT, BS, wc,            bq, q);
    gemm_proj<<<dim3(8, BS / 128), 256, SMEM_GEMM>>>(hsT, BS, wc + WOFF,     bk, kt);
    gemm_proj<<<dim3(8, BS / 128), 256, SMEM_GEMM>>>(hsT, BS, wc + 2 * WOFF, bv, vt);
    gemm_proj<<<dim3(8, BE / 128), 256, SMEM_GEMM>>>(exT, BE, wc + WOFF,     bk, ke);
    gemm_proj<<<dim3(8, BE / 128), 256, SMEM_GEMM>>>(exT, BE, wc + 2 * WOFF, bv, ve);

    // Convert activations for scores / ctx
    conv_trans<<<dim3(BS / 64, Hh / 64), 256>>>(q,  qT,  BS, Hh);
    conv_trans<<<dim3(BE / 64, Hh / 64), 256>>>(ke, keT, BE, Hh);
    conv_pair<<<dim3(1, BE / 2), 256>>>(ve, veP, Hh, 1.0f);

    // Scores
    self_dot_kernel<<<BS / 8, 256>>>(q, kt, s0);
    gemm_scores<<<dim3(4, Ss / 128, Bb), 256, SMEM_GEMM>>>(qT, keT, sc);

    // Softmax (emits paired probs)
    softmax_kernel<<<BS, 128>>>(sc, s0, p2);

    // Context
    gemm_ctx<<<dim3(8, Ss / 128, Bb), 256>>>(p2, s0, veP, vt, out);
}

// round 11
// speedup vs baseline: 1.3409x; 1.1470x over previous
#include <cuda_runtime.h>
#include <cuda_fp16.h>
#include <cstdint>
#include <math.h>

// Problem dims (fixed)
#define Bb 4
#define Ss 2048
#define Ee 512
#define Hh 1024
#define BS (Bb*Ss)
#define BE (Bb*Ee)

// fp32 scratch
__device__ float g_q [BS*Hh];
__device__ float g_kt[BS*Hh];
__device__ float g_vt[BS*Hh];
__device__ float g_ke[BE*Hh];
__device__ float g_ve[BE*Hh];
__device__ float g_sc[(size_t)BS*512];       // raw ext scores
__device__ float g_s0[BS];                   // self score / prob
// (hi,lo) fp16x2 pair scratch (16B aligned for cp.async)
__device__ __align__(16) uint2 g_hsT[(Hh/2)*(size_t)BS];
__device__ __align__(16) uint2 g_exT[(Hh/2)*(size_t)BE];
__device__ __align__(16) uint2 g_wc [3*(Hh/2)*(size_t)Hh];
__device__ __align__(16) uint2 g_qT [(Hh/2)*(size_t)BS];
__device__ __align__(16) uint2 g_keT[(Hh/2)*(size_t)BE];
__device__ __align__(16) uint2 g_veP[(BE/2)*(size_t)Hh];
__device__ __align__(16) uint2 g_p2T[(size_t)(Ee/2)*BS];  // probs [kp][row]

#define WSCALE 32.0f
#define WINV   (1.0f / 32.0f)

// Split two fp32 (consecutive k) into packed fp16x2 hi + lo. low half = x.
__device__ __forceinline__ void split2(float x, float y,
                                       uint32_t &h, uint32_t &l)
{
    asm("cvt.rn.f16x2.f32 %0, %1, %2;" : "=r"(h) : "f"(y), "f"(x));
    __half2 hv = *reinterpret_cast<__half2*>(&h);
    float2 b = __half22float2(hv);
    asm("cvt.rn.f16x2.f32 %0, %1, %2;" : "=r"(l) : "f"(y - b.y), "f"(x - b.x));
}

__device__ __forceinline__ void mma16(float* d, const uint32_t* a,
                                      const uint32_t* b)
{
    asm volatile(
        "mma.sync.aligned.m16n8k16.row.col.f32.f16.f16.f32 "
        "{%0,%1,%2,%3}, {%4,%5,%6,%7}, {%8,%9}, {%0,%1,%2,%3};"
        : "+f"(d[0]), "+f"(d[1]), "+f"(d[2]), "+f"(d[3])
        : "r"(a[0]), "r"(a[1]), "r"(a[2]), "r"(a[3]),
          "r"(b[0]), "r"(b[1]));
}

__device__ __forceinline__ void cpa(uint32_t d, const void* s)
{
    asm volatile("cp.async.cg.shared.global [%0], [%1], 16;"
                 :: "r"(d), "l"(s) : "memory");
}
#define CP_COMMIT() asm volatile("cp.async.commit_group;" ::: "memory")
#define CP_WAIT2()  asm volatile("cp.async.wait_group 2;" ::: "memory")

// ---------------------------------------------------------------------------
// Convert kernels
// ---------------------------------------------------------------------------
// Wq/Wk/Wv [K][N] f32 -> wc + z*WOFF, [K/2][N] uint2, scaled by 32.
__global__ void conv_w(const float* __restrict__ W0,
                       const float* __restrict__ W1,
                       const float* __restrict__ W2,
                       uint2* __restrict__ dst)
{
    const int z = blockIdx.z;
    const float* src = (z == 0) ? W0 : (z == 1) ? W1 : W2;
    uint2* d0 = dst + (size_t)z * (Hh / 2) * Hh;
    int kp = blockIdx.y;
    int n0 = threadIdx.x * 4;
    float4 r0 = *(const float4*)(src + (size_t)(2 * kp) * Hh + n0);
    float4 r1 = *(const float4*)(src + (size_t)(2 * kp + 1) * Hh + n0);
    uint2 o[4];
    split2(WSCALE * r0.x, WSCALE * r1.x, o[0].x, o[0].y);
    split2(WSCALE * r0.y, WSCALE * r1.y, o[1].x, o[1].y);
    split2(WSCALE * r0.z, WSCALE * r1.z, o[2].x, o[2].y);
    split2(WSCALE * r0.w, WSCALE * r1.w, o[3].x, o[3].y);
    uint2* d = d0 + (size_t)kp * Hh + n0;
    *(uint4*)d       = *(uint4*)&o[0];
    *(uint4*)(d + 2) = *(uint4*)&o[2];
}

// src [K][N] f32 -> dst [K/2][N] uint2, scale 1 (for ve).
__global__ void conv_pair(const float* __restrict__ src,
                          uint2* __restrict__ dst, int N)
{
    int kp = blockIdx.y;
    int n0 = (blockIdx.x * 256 + threadIdx.x) * 4;
    if (n0 >= N) return;
    float4 r0 = *(const float4*)(src + (size_t)(2 * kp) * N + n0);
    float4 r1 = *(const float4*)(src + (size_t)(2 * kp + 1) * N + n0);
    uint2 o[4];
    split2(r0.x, r1.x, o[0].x, o[0].y);
    split2(r0.y, r1.y, o[1].x, o[1].y);
    split2(r0.z, r1.z, o[2].x, o[2].y);
    split2(r0.w, r1.w, o[3].x, o[3].y);
    uint2* d = dst + (size_t)kp * N + n0;
    *(uint4*)d       = *(uint4*)&o[0];
    *(uint4*)(d + 2) = *(uint4*)&o[2];
}

// src [M][K] f32 -> dst [K/2][M] uint2 (transpose + split). 64x64 tiles.
__global__ void conv_trans(const float* __restrict__ src,
                           uint2* __restrict__ dst, int M, int K)
{
    __shared__ float t[64][65];
    const int m0 = blockIdx.x * 64;
    const int k0 = blockIdx.y * 64;
    const int tid = threadIdx.x;
    const int mr = tid >> 2;
    const int kc = (tid & 3) * 4;
    #pragma unroll
    for (int i = 0; i < 4; i++) {
        float4 v = *(const float4*)(src + (size_t)(m0 + mr) * K
                                    + k0 + (kc + i) * 4);
        t[mr][(kc + i) * 4 + 0] = v.x;
        t[mr][(kc + i) * 4 + 1] = v.y;
        t[mr][(kc + i) * 4 + 2] = v.z;
        t[mr][(kc + i) * 4 + 3] = v.w;
    }
    __syncthreads();
    const int kp = tid >> 3;
    const int ms = (tid & 7) * 8;
    uint2 o[8];
    #pragma unroll
    for (int j = 0; j < 8; j++)
        split2(t[ms + j][2 * kp], t[ms + j][2 * kp + 1], o[j].x, o[j].y);
    uint2* d = dst + (size_t)(k0 / 2 + kp) * M + m0 + ms;
    *(uint4*)(d)     = *(uint4*)&o[0];
    *(uint4*)(d + 2) = *(uint4*)&o[2];
    *(uint4*)(d + 4) = *(uint4*)&o[4];
    *(uint4*)(d + 6) = *(uint4*)&o[6];
}

// ---------------------------------------------------------------------------
// GEMM core: 256 threads, 128x128 tile, BK=16 (8 kp/stage), cp.async pipe
// ---------------------------------------------------------------------------
#define RP 132
#define STG_U2 (8 * RP)
#define STAGES 4
#define SMEM_GEMM (STAGES * STG_U2 * 2 * 8)   // 67584 B

#define FRAG_COMPUTE(Abuf, Bbuf)                                              \
  do {                                                                        \
    uint32_t ah[4][4], al[4][4], bh[4][2], bl[4][2];                          \
    _Pragma("unroll")                                                         \
    for (int mt = 0; mt < 4; mt++) {                                          \
      int mb = wm * 64 + mt * 16 + gid;                                       \
      uint2 v00 = (Abuf)[tg * RP + mb];                                       \
      uint2 v01 = (Abuf)[tg * RP + mb + 8];                                   \
      uint2 v10 = (Abuf)[(tg + 4) * RP + mb];                                 \
      uint2 v11 = (Abuf)[(tg + 4) * RP + mb + 8];                             \
      ah[mt][0] = v00.x; ah[mt][1] = v01.x;                                   \
      ah[mt][2] = v10.x; ah[mt][3] = v11.x;                                   \
      al[mt][0] = v00.y; al[mt][1] = v01.y;                                   \
      al[mt][2] = v10.y; al[mt][3] = v11.y;                                   \
    }                                                                         \
    _Pragma("unroll")                                                         \
    for (int nt = 0; nt < 4; nt++) {                                          \
      int nb = wn * 32 + nt * 8 + gid;                                        \
      uint2 w0 = (Bbuf)[tg * RP + nb];                                        \
      uint2 w1 = (Bbuf)[(tg + 4) * RP + nb];                                  \
      bh[nt][0] = w0.x; bh[nt][1] = w1.x;                                     \
      bl[nt][0] = w0.y; bl[nt][1] = w1.y;                                     \
    }                                                                         \
    _Pragma("unroll")                                                         \
    for (int mt = 0; mt < 4; mt++)                                            \
      _Pragma("unroll")                                                       \
      for (int nt = 0; nt < 4; nt++) {                                        \
        mma16(acc[mt][nt], ah[mt], bh[nt]);                                   \
        mma16(acc[mt][nt], ah[mt], bl[nt]);                                   \
        mma16(acc[mt][nt], al[mt], bh[nt]);                                   \
      }                                                                       \
  } while (0)

#define ACC_INIT                                                              \
    float acc[4][4][4];                                                      \
    _Pragma("unroll")                                                         \
    for (int i = 0; i < 4; i++)                                               \
      _Pragma("unroll")                                                       \
      for (int j = 0; j < 4; j++)                                             \
        _Pragma("unroll")                                                     \
        for (int t = 0; t < 4; t++) acc[i][j][t] = 0.f;

#define WARP_IDS                                                              \
    const int tid = threadIdx.x;                                              \
    const int warp = tid >> 5, lane = tid & 31;                               \
    const int wm = warp & 1, wn = warp >> 1;                                  \
    const int gid = lane >> 2, tg = lane & 3;

#define PIPE_SMEM                                                             \
    extern __shared__ uint2 dsm[];                                            \
    uint2* const Asm = dsm;                                                   \
    uint2* const Bsm = dsm + STAGES * STG_U2;                                 \
    uint32_t smb;                                                             \
    asm("{ .reg .u64 t; cvta.to.shared.u64 t, %1; cvt.u32.u64 %0, t; }"       \
        : "=r"(smb) : "l"(dsm));                                              \
    const uint32_t sA = smb;                                                  \
    const uint32_t sB = smb + STAGES * STG_U2 * 8;

#define ISSUE_AB(s, kp0)                                                      \
    do {                                                                      \
        const uint2* ap_ = Abase + (size_t)((kp0) + crow) * ldA + ccol;       \
        uint32_t da_ = sA + ((s) * STG_U2 + crow * RP + ccol) * 8;            \
        cpa(da_, ap_);                                                        \
        cpa(da_ + 16, ap_ + 2);                                               \
        const uint2* bp_ = Bbase + (size_t)((kp0) + crow) * ldB + ccol;       \
        uint32_t db_ = sB + ((s) * STG_U2 + crow * RP + ccol) * 8;            \
        cpa(db_, bp_);                                                        \
        cpa(db_ + 16, bp_ + 2);                                               \
    } while (0)

// One sync per stage; next-stage issue precedes compute (overlap).
#define PIPE_MAINLOOP(NST)                                                    \
    ISSUE_AB(0, 0); CP_COMMIT();                                              \
    ISSUE_AB(1, 8); CP_COMMIT();                                              \
    ISSUE_AB(2, 16); CP_COMMIT();                                             \
    for (int i = 0; i < (NST); i++) {                                         \
        CP_WAIT2();                                                           \
        __syncthreads();                                                      \
        int buf = i & 3;                                                      \
        if (i + 3 < (NST)) ISSUE_AB((i + 3) & 3, (i + 3) * 8);                \
        CP_COMMIT();                                                          \
        FRAG_COMPUTE((Asm + buf * STG_U2), (Bsm + buf * STG_U2));             \
    }

// ---------------------------------------------------------------------------
// Merged projections: z in 0..4 selects {q, kt, vt, ke, ve}.
// ---------------------------------------------------------------------------
__global__ void __launch_bounds__(256, 2) gemm_proj_all(
    const uint2* __restrict__ hsT, const uint2* __restrict__ exT,
    const uint2* __restrict__ wc,
    const float* __restrict__ bq, const float* __restrict__ bk,
    const float* __restrict__ bv,
    float* __restrict__ q, float* __restrict__ kt, float* __restrict__ vt,
    float* __restrict__ ke, float* __restrict__ ve)
{
    const int z = blockIdx.z;
    const bool isExt = (z >= 3);
    if (isExt && blockIdx.y >= 16) return;

    PIPE_SMEM;
    const uint2* AT  = isExt ? exT : hsT;
    const int ldA    = isExt ? BE : BS;
    const int wsel   = isExt ? (z - 2) : z;
    const uint2* BP  = wc + (size_t)wsel * (Hh / 2) * Hh;
    const float* bias = (wsel == 0) ? bq : (wsel == 1) ? bk : bv;
    float* C = (z == 0) ? q : (z == 1) ? kt : (z == 2) ? vt
             : (z == 3) ? ke : ve;

    const int bm = blockIdx.y * 128;
    const int bn = blockIdx.x * 128;
    WARP_IDS;
    const int crow = tid >> 5;
    const int ccol = (tid & 31) * 4;
    const uint2* Abase = AT + bm;
    const uint2* Bbase = BP + bn;
    const int ldB = Hh;

    ACC_INIT;
    PIPE_MAINLOOP(Hh / 16);

    #pragma unroll
    for (int mt = 0; mt < 4; mt++) {
        int r0 = bm + wm * 64 + mt * 16 + gid;
        #pragma unroll
        for (int nt = 0; nt < 4; nt++) {
            int col = bn + wn * 32 + nt * 8 + 2 * tg;
            float2 bi = *(const float2*)(bias + col);
            float2 o0 = make_float2(fmaf(acc[mt][nt][0], WINV, bi.x),
                                    fmaf(acc[mt][nt][1], WINV, bi.y));
            float2 o1 = make_float2(fmaf(acc[mt][nt][2], WINV, bi.x),
                                    fmaf(acc[mt][nt][3], WINV, bi.y));
            *(float2*)(C + (size_t)r0 * Hh + col) = o0;
            *(float2*)(C + (size_t)(r0 + 8) * Hh + col) = o1;
        }
    }
}

// ---------------------------------------------------------------------------
// Scores: SC[b, s, e] = Q . KE (K=1024).
// ---------------------------------------------------------------------------
__global__ void __launch_bounds__(256, 2) gemm_scores(
    const uint2* __restrict__ QT, const uint2* __restrict__ KT,
    float* __restrict__ SC)
{
    PIPE_SMEM;
    const int b = blockIdx.z;
    const int bm = b * Ss + blockIdx.y * 128;
    const int bn = b * Ee + blockIdx.x * 128;
    WARP_IDS;
    const int crow = tid >> 5;
    const int ccol = (tid & 31) * 4;
    const uint2* Abase = QT + bm;
    const uint2* Bbase = KT + bn;
    const int ldA = BS, ldB = BE;

    ACC_INIT;
    PIPE_MAINLOOP(Hh / 16);

    const int cb = blockIdx.x * 128;
    #pragma unroll
    for (int mt = 0; mt < 4; mt++) {
        int row = bm + wm * 64 + mt * 16 + gid;
        #pragma unroll
        for (int nt = 0; nt < 4; nt++) {
            int col = cb + wn * 32 + nt * 8 + 2 * tg;
            *(float2*)(SC + (size_t)row * 512 + col) =
                make_float2(acc[mt][nt][0], acc[mt][nt][1]);
            *(float2*)(SC + (size_t)(row + 8) * 512 + col) =
                make_float2(acc[mt][nt][2], acc[mt][nt][3]);
        }
    }
}

// ---------------------------------------------------------------------------
// Context: O = P @ VE + p0 * VT (K=512). P2T is [kp][row] — same pipeline.
// ---------------------------------------------------------------------------
__global__ void __launch_bounds__(256, 2) gemm_ctx(
    const uint2* __restrict__ P2T, const float* __restrict__ P0,
    const uint2* __restrict__ VP, const float* __restrict__ VT,
    float* __restrict__ O)
{
    PIPE_SMEM;
    const int b = blockIdx.z;
    const int bm = b * Ss + blockIdx.y * 128;
    const int bn = blockIdx.x * 128;
    WARP_IDS;
    const int crow = tid >> 5;
    const int ccol = (tid & 31) * 4;
    const uint2* Abase = P2T + bm;
    const uint2* Bbase = VP + (size_t)b * (Ee / 2) * Hh + bn;
    const int ldA = BS, ldB = Hh;

    ACC_INIT;
    PIPE_MAINLOOP(Ee / 16);

    #pragma unroll
    for (int mt = 0; mt < 4; mt++) {
        int r0 = bm + wm * 64 + mt * 16 + gid;
        int r1 = r0 + 8;
        float p0 = P0[r0];
        float p1 = P0[r1];
        #pragma unroll
        for (int nt = 0; nt < 4; nt++) {
            int col = bn + wn * 32 + nt * 8 + 2 * tg;
            float2 v0 = *(const float2*)(VT + (size_t)r0 * Hh + col);
            float2 v1 = *(const float2*)(VT + (size_t)r1 * Hh + col);
            float2 o0 = make_float2(fmaf(p0, v0.x, acc[mt][nt][0]),
                                    fmaf(p0, v0.y, acc[mt][nt][1]));
            float2 o1 = make_float2(fmaf(p1, v1.x, acc[mt][nt][2]),
                                    fmaf(p1, v1.y, acc[mt][nt][3]));
            *(float2*)(O + (size_t)r0 * Hh + col) = o0;
            *(float2*)(O + (size_t)r1 * Hh + col) = o1;
        }
    }
}

// ---------------------------------------------------------------------------
// Self-dot + softmax (softmax emits transposed paired probs)
// ---------------------------------------------------------------------------
__global__ void self_dot_kernel(const float* __restrict__ q,
                                const float* __restrict__ kt,
                                float* __restrict__ S0)
{
    int row  = blockIdx.x * 8 + (threadIdx.x >> 5);
    int lane = threadIdx.x & 31;
    const float4* q4 = (const float4*)(q  + (size_t)row * Hh);
    const float4* k4 = (const float4*)(kt + (size_t)row * Hh);
    float sum = 0.f;
    #pragma unroll
    for (int i = lane; i < Hh / 4; i += 32) {
        float4 a = q4[i], b = k4[i];
        sum += a.x * b.x + a.y * b.y + a.z * b.z + a.w * b.w;
    }
    #pragma unroll
    for (int o = 16; o; o >>= 1) sum += __shfl_xor_sync(0xffffffffu, sum, o);
    if (lane == 0) S0[row] = sum;
}

__global__ void softmax_kernel(const float* __restrict__ SC,
                               float* __restrict__ S0,
                               uint2* __restrict__ P2T)
{
    const int row = blockIdx.x;
    const float* s = SC + (size_t)row * 512;
    const int tid = threadIdx.x;
    __shared__ float redm[4], reds[4];

    float4 v = ((const float4*)s)[tid];
    float s0 = S0[row];
    float lmax = fmaxf(fmaxf(v.x, v.y), fmaxf(v.z, v.w));
    if (tid == 0) lmax = fmaxf(lmax, s0);
    #pragma unroll
    for (int o = 16; o; o >>= 1)
        lmax = fmaxf(lmax, __shfl_xor_sync(0xffffffffu, lmax, o));
    if ((tid & 31) == 0) redm[tid >> 5] = lmax;
    __syncthreads();
    float m = fmaxf(fmaxf(redm[0], redm[1]), fmaxf(redm[2], redm[3]));

    v.x = expf(v.x - m); v.y = expf(v.y - m);
    v.z = expf(v.z - m); v.w = expf(v.w - m);
    float e0 = expf(s0 - m);
    float lsum = v.x + v.y + v.z + v.w + ((tid == 0) ? e0 : 0.f);
    #pragma unroll
    for (int o = 16; o; o >>= 1) lsum += __shfl_xor_sync(0xffffffffu, lsum, o);
    if ((tid & 31) == 0) reds[tid >> 5] = lsum;
    __syncthreads();
    float inv = 1.f / (reds[0] + reds[1] + reds[2] + reds[3]);

    uint2 o0, o1;
    split2(v.x * inv, v.y * inv, o0.x, o0.y);
    split2(v.z * inv, v.w * inv, o1.x, o1.y);
    // transposed: P2T[kp][row], kp = 2*tid, 2*tid+1
    P2T[(size_t)(2 * tid) * BS + row]     = o0;
    P2T[(size_t)(2 * tid + 1) * BS + row] = o1;
    if (tid == 0) S0[row] = e0 * inv;
}

// ---------------------------------------------------------------------------
extern "C" void kernel_launch(void* const* d_in, const int* in_sizes, int n_in,
                              void* d_out, int out_size)
{
    const float* hs  = (const float*)d_in[0];
    const float* ext = (const float*)d_in[1];
    const float* Wq  = (const float*)d_in[2];
    const float* bq  = (const float*)d_in[3];
    const float* Wk  = (const float*)d_in[4];
    const float* bk  = (const float*)d_in[5];
    const float* Wv  = (const float*)d_in[6];
    const float* bv  = (const float*)d_in[7];
    float* out = (float*)d_out;

    float *q, *kt, *vt, *ke, *ve, *sc, *s0;
    uint2 *hsT, *exT, *wc, *qT, *keT, *veP, *p2T;
    cudaGetSymbolAddress((void**)&q,   g_q);
    cudaGetSymbolAddress((void**)&kt,  g_kt);
    cudaGetSymbolAddress((void**)&vt,  g_vt);
    cudaGetSymbolAddress((void**)&ke,  g_ke);
    cudaGetSymbolAddress((void**)&ve,  g_ve);
    cudaGetSymbolAddress((void**)&sc,  g_sc);
    cudaGetSymbolAddress((void**)&s0,  g_s0);
    cudaGetSymbolAddress((void**)&hsT, g_hsT);
    cudaGetSymbolAddress((void**)&exT, g_exT);
    cudaGetSymbolAddress((void**)&wc,  g_wc);
    cudaGetSymbolAddress((void**)&qT,  g_qT);
    cudaGetSymbolAddress((void**)&keT, g_keT);
    cudaGetSymbolAddress((void**)&veP, g_veP);
    cudaGetSymbolAddress((void**)&p2T, g_p2T);

    cudaFuncSetAttribute(gemm_proj_all,
        cudaFuncAttributeMaxDynamicSharedMemorySize, SMEM_GEMM);
    cudaFuncSetAttribute(gemm_scores,
        cudaFuncAttributeMaxDynamicSharedMemorySize, SMEM_GEMM);
    cudaFuncSetAttribute(gemm_ctx,
        cudaFuncAttributeMaxDynamicSharedMemorySize, SMEM_GEMM);

    // Pre-convert inputs
    conv_trans<<<dim3(BS / 64, Hh / 64), 256>>>(hs,  hsT, BS, Hh);
    conv_trans<<<dim3(BE / 64, Hh / 64), 256>>>(ext, exT, BE, Hh);
    conv_w<<<dim3(1, Hh / 2, 3), 256>>>(Wq, Wk, Wv, wc);

    // All 5 projections, one launch (z selects; ext z early-exits y>=16)
    gemm_proj_all<<<dim3(8, BS / 128, 5), 256, SMEM_GEMM>>>(
        hsT, exT, wc, bq, bk, bv, q, kt, vt, ke, ve);

    // Convert activations for scores / ctx
    conv_trans<<<dim3(BS / 64, Hh / 64), 256>>>(q,  qT,  BS, Hh);
    conv_trans<<<dim3(BE / 64, Hh / 64), 256>>>(ke, keT, BE, Hh);
    conv_pair<<<dim3(1, BE / 2), 256>>>(ve, veP, Hh);

    // Scores
    self_dot_kernel<<<BS / 8, 256>>>(q, kt, s0);
    gemm_scores<<<dim3(4, Ss / 128, Bb), 256, SMEM_GEMM>>>(qT, keT, sc);

    // Softmax (emits transposed paired probs)
    softmax_kernel<<<BS, 128>>>(sc, s0, p2T);

    // Context
    gemm_ctx<<<dim3(8, Ss / 128, Bb), 256, SMEM_GEMM>>>(p2T, s0, veP, vt, out);
}

// round 12
// speedup vs baseline: 1.3549x; 1.0104x over previous
#include <cuda_runtime.h>
#include <cuda_fp16.h>
#include <cstdint>
#include <math.h>

// Problem dims (fixed)
#define Bb 4
#define Ss 2048
#define Ee 512
#define Hh 1024
#define BS (Bb*Ss)
#define BE (Bb*Ee)

// fp32 scratch
__device__ float g_q [BS*Hh];
__device__ float g_kt[BS*Hh];
__device__ float g_vt[BS*Hh];
__device__ float g_ke[BE*Hh];
__device__ float g_ve[BE*Hh];
__device__ float g_sc[(size_t)BS*512];       // raw ext scores
__device__ float g_s0[BS];                   // self score / prob
// (hi,lo) fp16x2 pair scratch (16B aligned for cp.async)
__device__ __align__(16) uint2 g_hsT[(Hh/2)*(size_t)BS];
__device__ __align__(16) uint2 g_exT[(Hh/2)*(size_t)BE];
__device__ __align__(16) uint2 g_wc [3*(Hh/2)*(size_t)Hh];
__device__ __align__(16) uint2 g_qT [(Hh/2)*(size_t)BS];
__device__ __align__(16) uint2 g_keT[(Hh/2)*(size_t)BE];
__device__ __align__(16) uint2 g_veP[(BE/2)*(size_t)Hh];
__device__ __align__(16) uint2 g_p2T[(size_t)(Ee/2)*BS];  // probs [kp][row]

#define WSCALE 32.0f
#define WINV   (1.0f / 32.0f)

// Split two fp32 (consecutive k) into packed fp16x2 hi + lo. low half = x.
__device__ __forceinline__ void split2(float x, float y,
                                       uint32_t &h, uint32_t &l)
{
    asm("cvt.rn.f16x2.f32 %0, %1, %2;" : "=r"(h) : "f"(y), "f"(x));
    __half2 hv = *reinterpret_cast<__half2*>(&h);
    float2 b = __half22float2(hv);
    asm("cvt.rn.f16x2.f32 %0, %1, %2;" : "=r"(l) : "f"(y - b.y), "f"(x - b.x));
}

__device__ __forceinline__ void mma16(float* d, const uint32_t* a,
                                      const uint32_t* b)
{
    asm volatile(
        "mma.sync.aligned.m16n8k16.row.col.f32.f16.f16.f32 "
        "{%0,%1,%2,%3}, {%4,%5,%6,%7}, {%8,%9}, {%0,%1,%2,%3};"
        : "+f"(d[0]), "+f"(d[1]), "+f"(d[2]), "+f"(d[3])
        : "r"(a[0]), "r"(a[1]), "r"(a[2]), "r"(a[3]),
          "r"(b[0]), "r"(b[1]));
}

__device__ __forceinline__ void cpa(uint32_t d, const void* s)
{
    asm volatile("cp.async.cg.shared.global [%0], [%1], 16;"
                 :: "r"(d), "l"(s) : "memory");
}
#define CP_COMMIT() asm volatile("cp.async.commit_group;" ::: "memory")
#define CP_WAIT2()  asm volatile("cp.async.wait_group 2;" ::: "memory")

// ---------------------------------------------------------------------------
// Convert kernels
// ---------------------------------------------------------------------------
__global__ void conv_w(const float* __restrict__ W0,
                       const float* __restrict__ W1,
                       const float* __restrict__ W2,
                       uint2* __restrict__ dst)
{
    const int z = blockIdx.z;
    const float* src = (z == 0) ? W0 : (z == 1) ? W1 : W2;
    uint2* d0 = dst + (size_t)z * (Hh / 2) * Hh;
    int kp = blockIdx.y;
    int n0 = threadIdx.x * 4;
    float4 r0 = *(const float4*)(src + (size_t)(2 * kp) * Hh + n0);
    float4 r1 = *(const float4*)(src + (size_t)(2 * kp + 1) * Hh + n0);
    uint2 o[4];
    split2(WSCALE * r0.x, WSCALE * r1.x, o[0].x, o[0].y);
    split2(WSCALE * r0.y, WSCALE * r1.y, o[1].x, o[1].y);
    split2(WSCALE * r0.z, WSCALE * r1.z, o[2].x, o[2].y);
    split2(WSCALE * r0.w, WSCALE * r1.w, o[3].x, o[3].y);
    uint2* d = d0 + (size_t)kp * Hh + n0;
    *(uint4*)d       = *(uint4*)&o[0];
    *(uint4*)(d + 2) = *(uint4*)&o[2];
}

__global__ void conv_pair(const float* __restrict__ src,
                          uint2* __restrict__ dst, int N)
{
    int kp = blockIdx.y;
    int n0 = (blockIdx.x * 256 + threadIdx.x) * 4;
    if (n0 >= N) return;
    float4 r0 = *(const float4*)(src + (size_t)(2 * kp) * N + n0);
    float4 r1 = *(const float4*)(src + (size_t)(2 * kp + 1) * N + n0);
    uint2 o[4];
    split2(r0.x, r1.x, o[0].x, o[0].y);
    split2(r0.y, r1.y, o[1].x, o[1].y);
    split2(r0.z, r1.z, o[2].x, o[2].y);
    split2(r0.w, r1.w, o[3].x, o[3].y);
    uint2* d = dst + (size_t)kp * N + n0;
    *(uint4*)d       = *(uint4*)&o[0];
    *(uint4*)(d + 2) = *(uint4*)&o[2];
}

__global__ void conv_trans(const float* __restrict__ src,
                           uint2* __restrict__ dst, int M, int K)
{
    __shared__ float t[64][65];
    const int m0 = blockIdx.x * 64;
    const int k0 = blockIdx.y * 64;
    const int tid = threadIdx.x;
    const int mr = tid >> 2;
    const int kc = (tid & 3) * 4;
    #pragma unroll
    for (int i = 0; i < 4; i++) {
        float4 v = *(const float4*)(src + (size_t)(m0 + mr) * K
                                    + k0 + (kc + i) * 4);
        t[mr][(kc + i) * 4 + 0] = v.x;
        t[mr][(kc + i) * 4 + 1] = v.y;
        t[mr][(kc + i) * 4 + 2] = v.z;
        t[mr][(kc + i) * 4 + 3] = v.w;
    }
    __syncthreads();
    const int kp = tid >> 3;
    const int ms = (tid & 7) * 8;
    uint2 o[8];
    #pragma unroll
    for (int j = 0; j < 8; j++)
        split2(t[ms + j][2 * kp], t[ms + j][2 * kp + 1], o[j].x, o[j].y);
    uint2* d = dst + (size_t)(k0 / 2 + kp) * M + m0 + ms;
    *(uint4*)(d)     = *(uint4*)&o[0];
    *(uint4*)(d + 2) = *(uint4*)&o[2];
    *(uint4*)(d + 4) = *(uint4*)&o[4];
    *(uint4*)(d + 6) = *(uint4*)&o[6];
}

// ---------------------------------------------------------------------------
// GEMM core: 256 threads, 128x128 tile, BK=16 (8 kp/stage), cp.async pipe,
// 4x-unrolled mainloop => compile-time smem addressing.
// ---------------------------------------------------------------------------
#define RP 132
#define STG_U2 (8 * RP)
#define STAGES 4
#define SMEM_GEMM (STAGES * STG_U2 * 2 * 8)   // 67584 B

#define FRAG_COMPUTE(Abuf, Bbuf)                                              \
  do {                                                                        \
    uint32_t ah[4][4], al[4][4], bh[4][2], bl[4][2];                          \
    _Pragma("unroll")                                                         \
    for (int mt = 0; mt < 4; mt++) {                                          \
      int mb = wm * 64 + mt * 16 + gid;                                       \
      uint2 v00 = (Abuf)[tg * RP + mb];                                       \
      uint2 v01 = (Abuf)[tg * RP + mb + 8];                                   \
      uint2 v10 = (Abuf)[(tg + 4) * RP + mb];                                 \
      uint2 v11 = (Abuf)[(tg + 4) * RP + mb + 8];                             \
      ah[mt][0] = v00.x; ah[mt][1] = v01.x;                                   \
      ah[mt][2] = v10.x; ah[mt][3] = v11.x;                                   \
      al[mt][0] = v00.y; al[mt][1] = v01.y;                                   \
      al[mt][2] = v10.y; al[mt][3] = v11.y;                                   \
    }                                                                         \
    _Pragma("unroll")                                                         \
    for (int nt = 0; nt < 4; nt++) {                                          \
      int nb = wn * 32 + nt * 8 + gid;                                        \
      uint2 w0 = (Bbuf)[tg * RP + nb];                                        \
      uint2 w1 = (Bbuf)[(tg + 4) * RP + nb];                                  \
      bh[nt][0] = w0.x; bh[nt][1] = w1.x;                                     \
      bl[nt][0] = w0.y; bl[nt][1] = w1.y;                                     \
    }                                                                         \
    _Pragma("unroll")                                                         \
    for (int mt = 0; mt < 4; mt++)                                            \
      _Pragma("unroll")                                                       \
      for (int nt = 0; nt < 4; nt++) {                                        \
        mma16(acc[mt][nt], ah[mt], bh[nt]);                                   \
        mma16(acc[mt][nt], ah[mt], bl[nt]);                                   \
        mma16(acc[mt][nt], al[mt], bh[nt]);                                   \
      }                                                                       \
  } while (0)

#define ACC_INIT                                                              \
    float acc[4][4][4];                                                      \
    _Pragma("unroll")                                                         \
    for (int i = 0; i < 4; i++)                                               \
      _Pragma("unroll")                                                       \
      for (int j = 0; j < 4; j++)                                             \
        _Pragma("unroll")                                                     \
        for (int t = 0; t < 4; t++) acc[i][j][t] = 0.f;

#define WARP_IDS                                                              \
    const int tid = threadIdx.x;                                              \
    const int warp = tid >> 5, lane = tid & 31;                               \
    const int wm = warp & 1, wn = warp >> 1;                                  \
    const int gid = lane >> 2, tg = lane & 3;

#define PIPE_SMEM                                                             \
    extern __shared__ uint2 dsm[];                                            \
    uint2* const Asm = dsm;                                                   \
    uint2* const Bsm = dsm + STAGES * STG_U2;                                 \
    uint32_t smb;                                                             \
    asm("{ .reg .u64 t; cvta.to.shared.u64 t, %1; cvt.u32.u64 %0, t; }"       \
        : "=r"(smb) : "l"(dsm));

// Running-pointer issue: stage slot s is compile-time.
#define ISSUE_S(s)                                                            \
    do {                                                                      \
        cpa(dA0 + (s) * (STG_U2 * 8), aPtr);                                  \
        cpa(dA0 + (s) * (STG_U2 * 8) + 16, aPtr + 2);                         \
        cpa(dB0 + (s) * (STG_U2 * 8), bPtr);                                  \
        cpa(dB0 + (s) * (STG_U2 * 8) + 16, bPtr + 2);                         \
        aPtr += (size_t)8 * ldA;                                              \
        bPtr += (size_t)8 * ldB;                                              \
    } while (0)

// NST must be a multiple of 4.
#define PIPE_MAINLOOP(NST)                                                    \
    const uint32_t dA0 = smb + (crow * RP + ccol) * 8;                        \
    const uint32_t dB0 = smb + STAGES * STG_U2 * 8 + (crow * RP + ccol) * 8;  \
    const uint2* aPtr = Abase + (size_t)crow * ldA + ccol;                    \
    const uint2* bPtr = Bbase + (size_t)crow * ldB + ccol;                    \
    ISSUE_S(0); CP_COMMIT();                                                  \
    ISSUE_S(1); CP_COMMIT();                                                  \
    ISSUE_S(2); CP_COMMIT();                                                  \
    for (int i = 0; i < (NST); i += 4) {                                      \
        _Pragma("unroll")                                                     \
        for (int j = 0; j < 4; j++) {                                         \
            CP_WAIT2();                                                       \
            __syncthreads();                                                  \
            if (i + j + 3 < (NST)) ISSUE_S((j + 3) & 3);                      \
            CP_COMMIT();                                                      \
            FRAG_COMPUTE((Asm + j * STG_U2), (Bsm + j * STG_U2));             \
        }                                                                     \
    }

// ---------------------------------------------------------------------------
// Merged projections: z in 0..4 selects {q, kt, vt, ke, ve}.
// ---------------------------------------------------------------------------
__global__ void __launch_bounds__(256, 2) gemm_proj_all(
    const uint2* __restrict__ hsT, const uint2* __restrict__ exT,
    const uint2* __restrict__ wc,
    const float* __restrict__ bq, const float* __restrict__ bk,
    const float* __restrict__ bv,
    float* __restrict__ q, float* __restrict__ kt, float* __restrict__ vt,
    float* __restrict__ ke, float* __restrict__ ve)
{
    const int z = blockIdx.z;
    const bool isExt = (z >= 3);
    if (isExt && blockIdx.y >= 16) return;

    PIPE_SMEM;
    const uint2* AT  = isExt ? exT : hsT;
    const int ldA    = isExt ? BE : BS;
    const int wsel   = isExt ? (z - 2) : z;
    const uint2* BP  = wc + (size_t)wsel * (Hh / 2) * Hh;
    const float* bias = (wsel == 0) ? bq : (wsel == 1) ? bk : bv;
    float* C = (z == 0) ? q : (z == 1) ? kt : (z == 2) ? vt
             : (z == 3) ? ke : ve;

    const int bm = blockIdx.y * 128;
    const int bn = blockIdx.x * 128;
    WARP_IDS;
    const int crow = tid >> 5;
    const int ccol = (tid & 31) * 4;
    const uint2* Abase = AT + bm;
    const uint2* Bbase = BP + bn;
    const int ldB = Hh;

    ACC_INIT;
    PIPE_MAINLOOP(Hh / 16);

    #pragma unroll
    for (int mt = 0; mt < 4; mt++) {
        int r0 = bm + wm * 64 + mt * 16 + gid;
        #pragma unroll
        for (int nt = 0; nt < 4; nt++) {
            int col = bn + wn * 32 + nt * 8 + 2 * tg;
            float2 bi = *(const float2*)(bias + col);
            float2 o0 = make_float2(fmaf(acc[mt][nt][0], WINV, bi.x),
                                    fmaf(acc[mt][nt][1], WINV, bi.y));
            float2 o1 = make_float2(fmaf(acc[mt][nt][2], WINV, bi.x),
                                    fmaf(acc[mt][nt][3], WINV, bi.y));
            *(float2*)(C + (size_t)r0 * Hh + col) = o0;
            *(float2*)(C + (size_t)(r0 + 8) * Hh + col) = o1;
        }
    }
}

// ---------------------------------------------------------------------------
// Scores: SC[b, s, e] = Q . KE (K=1024).
// ---------------------------------------------------------------------------
__global__ void __launch_bounds__(256, 2) gemm_scores(
    const uint2* __restrict__ QT, const uint2* __restrict__ KT,
    float* __restrict__ SC)
{
    PIPE_SMEM;
    const int b = blockIdx.z;
    const int bm = b * Ss + blockIdx.y * 128;
    const int bn = b * Ee + blockIdx.x * 128;
    WARP_IDS;
    const int crow = tid >> 5;
    const int ccol = (tid & 31) * 4;
    const uint2* Abase = QT + bm;
    const uint2* Bbase = KT + bn;
    const int ldA = BS, ldB = BE;

    ACC_INIT;
    PIPE_MAINLOOP(Hh / 16);

    const int cb = blockIdx.x * 128;
    #pragma unroll
    for (int mt = 0; mt < 4; mt++) {
        int row = bm + wm * 64 + mt * 16 + gid;
        #pragma unroll
        for (int nt = 0; nt < 4; nt++) {
            int col = cb + wn * 32 + nt * 8 + 2 * tg;
            *(float2*)(SC + (size_t)row * 512 + col) =
                make_float2(acc[mt][nt][0], acc[mt][nt][1]);
            *(float2*)(SC + (size_t)(row + 8) * 512 + col) =
                make_float2(acc[mt][nt][2], acc[mt][nt][3]);
        }
    }
}

// ---------------------------------------------------------------------------
// Context: O = P @ VE + p0 * VT (K=512). P2T is [kp][row].
// ---------------------------------------------------------------------------
__global__ void __launch_bounds__(256, 2) gemm_ctx(
    const uint2* __restrict__ P2T, const float* __restrict__ P0,
    const uint2* __restrict__ VP, const float* __restrict__ VT,
    float* __restrict__ O)
{
    PIPE_SMEM;
    const int b = blockIdx.z;
    const int bm = b * Ss + blockIdx.y * 128;
    const int bn = blockIdx.x * 128;
    WARP_IDS;
    const int crow = tid >> 5;
    const int ccol = (tid & 31) * 4;
    const uint2* Abase = P2T + bm;
    const uint2* Bbase = VP + (size_t)b * (Ee / 2) * Hh + bn;
    const int ldA = BS, ldB = Hh;

    ACC_INIT;
    PIPE_MAINLOOP(Ee / 16);

    #pragma unroll
    for (int mt = 0; mt < 4; mt++) {
        int r0 = bm + wm * 64 + mt * 16 + gid;
        int r1 = r0 + 8;
        float p0 = P0[r0];
        float p1 = P0[r1];
        #pragma unroll
        for (int nt = 0; nt < 4; nt++) {
            int col = bn + wn * 32 + nt * 8 + 2 * tg;
            float2 v0 = *(const float2*)(VT + (size_t)r0 * Hh + col);
            float2 v1 = *(const float2*)(VT + (size_t)r1 * Hh + col);
            float2 o0 = make_float2(fmaf(p0, v0.x, acc[mt][nt][0]),
                                    fmaf(p0, v0.y, acc[mt][nt][1]));
            float2 o1 = make_float2(fmaf(p1, v1.x, acc[mt][nt][2]),
                                    fmaf(p1, v1.y, acc[mt][nt][3]));
            *(float2*)(O + (size_t)r0 * Hh + col) = o0;
            *(float2*)(O + (size_t)r1 * Hh + col) = o1;
        }
    }
}

// ---------------------------------------------------------------------------
// Self-dot + softmax
// ---------------------------------------------------------------------------
__global__ void self_dot_kernel(const float* __restrict__ q,
                                const float* __restrict__ kt,
                                float* __restrict__ S0)
{
    int row  = blockIdx.x * 8 + (threadIdx.x >> 5);
    int lane = threadIdx.x & 31;
    const float4* q4 = (const float4*)(q  + (size_t)row * Hh);
    const float4* k4 = (const float4*)(kt + (size_t)row * Hh);
    float sum = 0.f;
    #pragma unroll
    for (int i = lane; i < Hh / 4; i += 32) {
        float4 a = q4[i], b = k4[i];
        sum += a.x * b.x + a.y * b.y + a.z * b.z + a.w * b.w;
    }
    #pragma unroll
    for (int o = 16; o; o >>= 1) sum += __shfl_xor_sync(0xffffffffu, sum, o);
    if (lane == 0) S0[row] = sum;
}

__global__ void softmax_kernel(const float* __restrict__ SC,
                               float* __restrict__ S0,
                               uint2* __restrict__ P2T)
{
    const int row = blockIdx.x;
    const float* s = SC + (size_t)row * 512;
    const int tid = threadIdx.x;
    __shared__ float redm[4], reds[4];

    float4 v = ((const float4*)s)[tid];
    float s0 = S0[row];
    float lmax = fmaxf(fmaxf(v.x, v.y), fmaxf(v.z, v.w));
    if (tid == 0) lmax = fmaxf(lmax, s0);
    #pragma unroll
    for (int o = 16; o; o >>= 1)
        lmax = fmaxf(lmax, __shfl_xor_sync(0xffffffffu, lmax, o));
    if ((tid & 31) == 0) redm[tid >> 5] = lmax;
    __syncthreads();
    float m = fmaxf(fmaxf(redm[0], redm[1]), fmaxf(redm[2], redm[3]));

    v.x = expf(v.x - m); v.y = expf(v.y - m);
    v.z = expf(v.z - m); v.w = expf(v.w - m);
    float e0 = expf(s0 - m);
    float lsum = v.x + v.y + v.z + v.w + ((tid == 0) ? e0 : 0.f);
    #pragma unroll
    for (int o = 16; o; o >>= 1) lsum += __shfl_xor_sync(0xffffffffu, lsum, o);
    if ((tid & 31) == 0) reds[tid >> 5] = lsum;
    __syncthreads();
    float inv = 1.f / (reds[0] + reds[1] + reds[2] + reds[3]);

    uint2 o0, o1;
    split2(v.x * inv, v.y * inv, o0.x, o0.y);
    split2(v.z * inv, v.w * inv, o1.x, o1.y);
    P2T[(size_t)(2 * tid) * BS + row]     = o0;
    P2T[(size_t)(2 * tid + 1) * BS + row] = o1;
    if (tid == 0) S0[row] = e0 * inv;
}

// ---------------------------------------------------------------------------
extern "C" void kernel_launch(void* const* d_in, const int* in_sizes, int n_in,
                              void* d_out, int out_size)
{
    const float* hs  = (const float*)d_in[0];
    const float* ext = (const float*)d_in[1];
    const float* Wq  = (const float*)d_in[2];
    const float* bq  = (const float*)d_in[3];
    const float* Wk  = (const float*)d_in[4];
    const float* bk  = (const float*)d_in[5];
    const float* Wv  = (const float*)d_in[6];
    const float* bv  = (const float*)d_in[7];
    float* out = (float*)d_out;

    float *q, *kt, *vt, *ke, *ve, *sc, *s0;
    uint2 *hsT, *exT, *wc, *qT, *keT, *veP, *p2T;
    cudaGetSymbolAddress((void**)&q,   g_q);
    cudaGetSymbolAddress((void**)&kt,  g_kt);
    cudaGetSymbolAddress((void**)&vt,  g_vt);
    cudaGetSymbolAddress((void**)&ke,  g_ke);
    cudaGetSymbolAddress((void**)&ve,  g_ve);
    cudaGetSymbolAddress((void**)&sc,  g_sc);
    cudaGetSymbolAddress((void**)&s0,  g_s0);
    cudaGetSymbolAddress((void**)&hsT, g_hsT);
    cudaGetSymbolAddress((void**)&exT, g_exT);
    cudaGetSymbolAddress((void**)&wc,  g_wc);
    cudaGetSymbolAddress((void**)&qT,  g_qT);
    cudaGetSymbolAddress((void**)&keT, g_keT);
    cudaGetSymbolAddress((void**)&veP, g_veP);
    cudaGetSymbolAddress((void**)&p2T, g_p2T);

    cudaFuncSetAttribute(gemm_proj_all,
        cudaFuncAttributeMaxDynamicSharedMemorySize, SMEM_GEMM);
    cudaFuncSetAttribute(gemm_scores,
        cudaFuncAttributeMaxDynamicSharedMemorySize, SMEM_GEMM);
    cudaFuncSetAttribute(gemm_ctx,
        cudaFuncAttributeMaxDynamicSharedMemorySize, SMEM_GEMM);

    // Pre-convert inputs
    conv_trans<<<dim3(BS / 64, Hh / 64), 256>>>(hs,  hsT, BS, Hh);
    conv_trans<<<dim3(BE / 64, Hh / 64), 256>>>(ext, exT, BE, Hh);
    conv_w<<<dim3(1, Hh / 2, 3), 256>>>(Wq, Wk, Wv, wc);

    // All 5 projections, one launch
    gemm_proj_all<<<dim3(8, BS / 128, 5), 256, SMEM_GEMM>>>(
        hsT, exT, wc, bq, bk, bv, q, kt, vt, ke, ve);

    // Convert activations for scores / ctx
    conv_trans<<<dim3(BS / 64, Hh / 64), 256>>>(q,  qT,  BS, Hh);
    conv_trans<<<dim3(BE / 64, Hh / 64), 256>>>(ke, keT, BE, Hh);
    conv_pair<<<dim3(1, BE / 2), 256>>>(ve, veP, Hh);

    // Scores
    self_dot_kernel<<<BS / 8, 256>>>(q, kt, s0);
    gemm_scores<<<dim3(4, Ss / 128, Bb), 256, SMEM_GEMM>>>(qT, keT, sc);

    // Softmax (emits transposed paired probs)
    softmax_kernel<<<BS, 128>>>(sc, s0, p2T);

    // Context
    gemm_ctx<<<dim3(8, Ss / 128, Bb), 256, SMEM_GEMM>>>(p2T, s0, veP, vt, out);
}

// round 13
// speedup vs baseline: 1.8985x; 1.4012x over previous
#include <cuda_runtime.h>
#include <cuda_fp16.h>
#include <cstdint>
#include <math.h>

// Problem dims (fixed)
#define Bb 4
#define Ss 2048
#define Ee 512
#define Hh 1024
#define BS (Bb*Ss)
#define BE (Bb*Ee)

// fp32 scratch
__device__ float g_q [BS*Hh];
__device__ float g_kt[BS*Hh];
__device__ float g_vt[BS*Hh];
__device__ float g_ke[BE*Hh];
__device__ float g_ve[BE*Hh];
__device__ float g_sc[(size_t)BS*512];       // raw ext scores
__device__ float g_s0[BS];                   // self score / prob
// Fragment-major (hi,lo separated) scratch.
// A-frag: per (k16,m16) block: 32 x uint4 hi, 32 x uint4 lo (1024 B)
// B-frag: per (k16,n8)  block: 32 x uint2 hi, 32 x uint2 lo (512 B)
__device__ __align__(16) uint4 g_hsF[(size_t)BS*Hh/4];
__device__ __align__(16) uint4 g_exF[(size_t)BE*Hh/4];
__device__ __align__(16) uint4 g_qF [(size_t)BS*Hh/4];
__device__ __align__(16) uint4 g_pF [(size_t)BS*512/4];
__device__ __align__(16) uint2 g_wF [3*(size_t)Hh*Hh/2];
__device__ __align__(16) uint2 g_keF[(size_t)Hh*BE/2];
__device__ __align__(16) uint2 g_veF[(size_t)BE*Hh/2];

#define WSCALE 32.0f
#define WINV   (1.0f / 32.0f)

// Split two fp32 (consecutive k) into packed fp16x2 hi + lo. low half = x.
__device__ __forceinline__ void split2(float x, float y,
                                       uint32_t &h, uint32_t &l)
{
    asm("cvt.rn.f16x2.f32 %0, %1, %2;" : "=r"(h) : "f"(y), "f"(x));
    __half2 hv = *reinterpret_cast<__half2*>(&h);
    float2 b = __half22float2(hv);
    asm("cvt.rn.f16x2.f32 %0, %1, %2;" : "=r"(l) : "f"(y - b.y), "f"(x - b.x));
}

__device__ __forceinline__ void mma16(float* d, const uint32_t* a,
                                      const uint32_t* b)
{
    asm volatile(
        "mma.sync.aligned.m16n8k16.row.col.f32.f16.f16.f32 "
        "{%0,%1,%2,%3}, {%4,%5,%6,%7}, {%8,%9}, {%0,%1,%2,%3};"
        : "+f"(d[0]), "+f"(d[1]), "+f"(d[2]), "+f"(d[3])
        : "r"(a[0]), "r"(a[1]), "r"(a[2]), "r"(a[3]),
          "r"(b[0]), "r"(b[1]));
}

__device__ __forceinline__ void cpa(uint32_t d, const void* s)
{
    asm volatile("cp.async.cg.shared.global [%0], [%1], 16;"
                 :: "r"(d), "l"(s) : "memory");
}
#define CP_COMMIT() asm volatile("cp.async.commit_group;" ::: "memory")
#define CP_WAIT2()  asm volatile("cp.async.wait_group 2;" ::: "memory")

// ---------------------------------------------------------------------------
// Convert kernels (64x64 fp32 tile staged in smem, then fragment emit)
// ---------------------------------------------------------------------------
#define TILE_LOAD(src, ld, r0, c0)                                            \
    do {                                                                      \
        int r_ = tid >> 2, c4_ = (tid & 3) * 16;                              \
        _Pragma("unroll")                                                     \
        for (int i_ = 0; i_ < 4; i_++) {                                      \
            float4 v_ = *(const float4*)((src) + (size_t)((r0) + r_) * (ld)   \
                                         + (c0) + c4_ + i_ * 4);              \
            t[r_][c4_ + i_*4 + 0] = v_.x;                                     \
            t[r_][c4_ + i_*4 + 1] = v_.y;                                     \
            t[r_][c4_ + i_*4 + 2] = v_.z;                                     \
            t[r_][c4_ + i_*4 + 3] = v_.w;                                     \
        }                                                                     \
    } while (0)

// A-frag from src [M][K] f32. grid (M/64, K/64), 256 thr.
__global__ void conv_A(const float* __restrict__ src, uint4* __restrict__ dst,
                       int M, int K)
{
    __shared__ float t[64][65];
    const int tid = threadIdx.x;
    const int m0 = blockIdx.x * 64, k0 = blockIdx.y * 64;
    TILE_LOAD(src, K, m0, k0);
    __syncthreads();
    #pragma unroll
    for (int j = 0; j < 2; j++) {
        int s = tid + j * 256;
        int kcl = s >> 7, m16l = (s >> 5) & 3, lane = s & 31;
        int gid = lane >> 2, tg = lane & 3;
        int ml = m16l * 16 + gid, kl = kcl * 16 + 2 * tg;
        uint4 h, l;
        split2(t[ml][kl],       t[ml][kl + 1],       h.x, l.x);
        split2(t[ml + 8][kl],   t[ml + 8][kl + 1],   h.y, l.y);
        split2(t[ml][kl + 8],   t[ml][kl + 9],       h.z, l.z);
        split2(t[ml + 8][kl + 8], t[ml + 8][kl + 9], h.w, l.w);
        size_t gb = (size_t)(k0 / 16 + kcl) * (M / 16) + (m0 / 16 + m16l);
        dst[gb * 64 + lane]      = h;
        dst[gb * 64 + 32 + lane] = l;
    }
}

// B-frag from src [K][N] f32 (scaled). grid (N/64, K/64), 256 thr.
__global__ void conv_B(const float* __restrict__ src, uint2* __restrict__ dst,
                       int K, int N, float scale)
{
    __shared__ float t[64][65];
    const int tid = threadIdx.x;
    const int n0 = blockIdx.x * 64, k0 = blockIdx.y * 64;
    TILE_LOAD(src, N, k0, n0);   // rows = k
    __syncthreads();
    #pragma unroll
    for (int j = 0; j < 4; j++) {
        int s = tid + j * 256;
        int kcl = s >> 8, n8l = (s >> 5) & 7, lane = s & 31;
        int gid = lane >> 2, tg = lane & 3;
        int nl = n8l * 8 + gid, kl = kcl * 16 + 2 * tg;
        uint2 h, l;
        split2(scale * t[kl][nl],     scale * t[kl + 1][nl], h.x, l.x);
        split2(scale * t[kl + 8][nl], scale * t[kl + 9][nl], h.y, l.y);
        size_t gb = (size_t)(k0 / 16 + kcl) * (N / 8) + (n0 / 8 + n8l);
        dst[gb * 64 + lane]      = h;
        dst[gb * 64 + 32 + lane] = l;
    }
}

// B-frag from transposed src [N][K] f32. grid (N/64, K/64), 256 thr.
__global__ void conv_BT(const float* __restrict__ src, uint2* __restrict__ dst,
                        int N, int K)
{
    __shared__ float t[64][65];
    const int tid = threadIdx.x;
    const int n0 = blockIdx.x * 64, k0 = blockIdx.y * 64;
    TILE_LOAD(src, K, n0, k0);   // rows = n
    __syncthreads();
    #pragma unroll
    for (int j = 0; j < 4; j++) {
        int s = tid + j * 256;
        int kcl = s >> 8, n8l = (s >> 5) & 7, lane = s & 31;
        int gid = lane >> 2, tg = lane & 3;
        int nl = n8l * 8 + gid, kl = kcl * 16 + 2 * tg;
        uint2 h, l;
        split2(t[nl][kl],     t[nl][kl + 1], h.x, l.x);
        split2(t[nl][kl + 8], t[nl][kl + 9], h.y, l.y);
        size_t gb = (size_t)(k0 / 16 + kcl) * (N / 8) + (n0 / 8 + n8l);
        dst[gb * 64 + lane]      = h;
        dst[gb * 64 + 32 + lane] = l;
    }
}

// ---------------------------------------------------------------------------
// GEMM core: 256 threads, 128x128 tile, BK=16, cp.async pipe, frag-major smem
// ---------------------------------------------------------------------------
#define STAGES 4
#define A_STG 8192
#define B_STG 8192
#define SMEM_GEMM ((A_STG + B_STG) * STAGES)   // 65536

#define FRAG_COMPUTE(j)                                                       \
  do {                                                                        \
    uint4 ahq[4], alq[4];                                                     \
    uint2 bhp[4], blp[4];                                                     \
    _Pragma("unroll")                                                         \
    for (int mt = 0; mt < 4; mt++) {                                          \
      const char* p = dsm + (j) * A_STG + (wm * 4 + mt) * 1024 + lane * 16;   \
      ahq[mt] = *(const uint4*)p;                                             \
      alq[mt] = *(const uint4*)(p + 512);                                     \
    }                                                                         \
    _Pragma("unroll")                                                         \
    for (int nt = 0; nt < 4; nt++) {                                          \
      const char* p = dsm + STAGES * A_STG + (j) * B_STG                      \
                      + (wn * 4 + nt) * 512 + lane * 8;                       \
      bhp[nt] = *(const uint2*)p;                                             \
      blp[nt] = *(const uint2*)(p + 256);                                     \
    }                                                                         \
    _Pragma("unroll")                                                         \
    for (int mt = 0; mt < 4; mt++)                                            \
      _Pragma("unroll")                                                       \
      for (int nt = 0; nt < 4; nt++) {                                        \
        mma16(acc[mt][nt], (const uint32_t*)&ahq[mt], (const uint32_t*)&bhp[nt]); \
        mma16(acc[mt][nt], (const uint32_t*)&ahq[mt], (const uint32_t*)&blp[nt]); \
        mma16(acc[mt][nt], (const uint32_t*)&alq[mt], (const uint32_t*)&bhp[nt]); \
      }                                                                       \
  } while (0)

#define ACC_INIT                                                              \
    float acc[4][4][4];                                                      \
    _Pragma("unroll")                                                         \
    for (int i = 0; i < 4; i++)                                               \
      _Pragma("unroll")                                                       \
      for (int j = 0; j < 4; j++)                                             \
        _Pragma("unroll")                                                     \
        for (int t = 0; t < 4; t++) acc[i][j][t] = 0.f;

#define WARP_IDS                                                              \
    const int tid = threadIdx.x;                                              \
    const int warp = tid >> 5, lane = tid & 31;                               \
    const int wm = warp & 1, wn = warp >> 1;                                  \
    const int gid = lane >> 2, tg = lane & 3;

#define PIPE_SMEM                                                             \
    extern __shared__ char dsm[];                                             \
    uint32_t smb;                                                             \
    asm("{ .reg .u64 t; cvta.to.shared.u64 t, %1; cvt.u32.u64 %0, t; }"       \
        : "=r"(smb) : "l"(dsm));

#define ISSUE_S(s)                                                            \
    do {                                                                      \
        cpa(dA0 + (s) * A_STG, aPtr);                                         \
        cpa(dA0 + (s) * A_STG + 16, aPtr + 16);                               \
        cpa(dB0 + (s) * B_STG, bPtr);                                         \
        cpa(dB0 + (s) * B_STG + 16, bPtr + 16);                               \
        aPtr += aStride;                                                      \
        bPtr += bStride;                                                      \
    } while (0)

// NST must be a multiple of 4.
#define PIPE_MAINLOOP(NST)                                                    \
    const uint32_t dA0 = smb + tid * 32;                                      \
    const uint32_t dB0 = smb + STAGES * A_STG + tid * 32;                     \
    ISSUE_S(0); CP_COMMIT();                                                  \
    ISSUE_S(1); CP_COMMIT();                                                  \
    ISSUE_S(2); CP_COMMIT();                                                  \
    for (int i = 0; i < (NST); i += 4) {                                      \
        _Pragma("unroll")                                                     \
        for (int j = 0; j < 4; j++) {                                         \
            CP_WAIT2();                                                       \
            __syncthreads();                                                  \
            if (i + j + 3 < (NST)) ISSUE_S((j + 3) & 3);                      \
            CP_COMMIT();                                                      \
            FRAG_COMPUTE(j);                                                  \
        }                                                                     \
    }

// ---------------------------------------------------------------------------
// Merged projections: z in 0..4 selects {q, kt, vt, ke, ve}.
// ---------------------------------------------------------------------------
__global__ void __launch_bounds__(256, 2) gemm_proj_all(
    const uint4* __restrict__ hsF, const uint4* __restrict__ exF,
    const uint2* __restrict__ wF,
    const float* __restrict__ bq, const float* __restrict__ bk,
    const float* __restrict__ bv,
    float* __restrict__ q, float* __restrict__ kt, float* __restrict__ vt,
    float* __restrict__ ke, float* __restrict__ ve)
{
    const int z = blockIdx.z;
    const bool isExt = (z >= 3);
    if (isExt && blockIdx.y >= 16) return;

    PIPE_SMEM;
    const int ldM  = isExt ? BE : BS;
    const int wsel = isExt ? (z - 2) : z;
    const float* bias = (wsel == 0) ? bq : (wsel == 1) ? bk : bv;
    float* C = (z == 0) ? q : (z == 1) ? kt : (z == 2) ? vt
             : (z == 3) ? ke : ve;

    const int bm = blockIdx.y * 128;
    const int bn = blockIdx.x * 128;
    WARP_IDS;
    const char* aPtr = (const char*)(isExt ? exF : hsF)
                       + (size_t)(bm / 16) * 1024 + tid * 32;
    const char* bPtr = (const char*)(wF + (size_t)wsel * (Hh/16) * (Hh/8) * 64)
                       + (size_t)(bn / 8) * 512 + tid * 32;
    const size_t aStride = (size_t)(ldM / 16) * 1024;
    const size_t bStride = (size_t)(Hh / 8) * 512;

    ACC_INIT;
    PIPE_MAINLOOP(Hh / 16);

    #pragma unroll
    for (int mt = 0; mt < 4; mt++) {
        int r0 = bm + wm * 64 + mt * 16 + gid;
        #pragma unroll
        for (int nt = 0; nt < 4; nt++) {
            int col = bn + wn * 32 + nt * 8 + 2 * tg;
            float2 bi = *(const float2*)(bias + col);
            float2 o0 = make_float2(fmaf(acc[mt][nt][0], WINV, bi.x),
                                    fmaf(acc[mt][nt][1], WINV, bi.y));
            float2 o1 = make_float2(fmaf(acc[mt][nt][2], WINV, bi.x),
                                    fmaf(acc[mt][nt][3], WINV, bi.y));
            *(float2*)(C + (size_t)r0 * Hh + col) = o0;
            *(float2*)(C + (size_t)(r0 + 8) * Hh + col) = o1;
        }
    }
}

// ---------------------------------------------------------------------------
// Scores: SC[b, s, e] = Q . KE (K=1024).
// ---------------------------------------------------------------------------
__global__ void __launch_bounds__(256, 2) gemm_scores(
    const uint4* __restrict__ qF, const uint2* __restrict__ keF,
    float* __restrict__ SC)
{
    PIPE_SMEM;
    const int b = blockIdx.z;
    const int bm = b * Ss + blockIdx.y * 128;
    const int bn = b * Ee + blockIdx.x * 128;
    WARP_IDS;
    const char* aPtr = (const char*)qF + (size_t)(bm / 16) * 1024 + tid * 32;
    const char* bPtr = (const char*)keF + (size_t)(bn / 8) * 512 + tid * 32;
    const size_t aStride = (size_t)(BS / 16) * 1024;
    const size_t bStride = (size_t)(BE / 8) * 512;

    ACC_INIT;
    PIPE_MAINLOOP(Hh / 16);

    const int cb = blockIdx.x * 128;
    #pragma unroll
    for (int mt = 0; mt < 4; mt++) {
        int row = bm + wm * 64 + mt * 16 + gid;
        #pragma unroll
        for (int nt = 0; nt < 4; nt++) {
            int col = cb + wn * 32 + nt * 8 + 2 * tg;
            *(float2*)(SC + (size_t)row * 512 + col) =
                make_float2(acc[mt][nt][0], acc[mt][nt][1]);
            *(float2*)(SC + (size_t)(row + 8) * 512 + col) =
                make_float2(acc[mt][nt][2], acc[mt][nt][3]);
        }
    }
}

// ---------------------------------------------------------------------------
// Context: O = P @ VE + p0 * VT (K=512).
// ---------------------------------------------------------------------------
__global__ void __launch_bounds__(256, 2) gemm_ctx(
    const uint4* __restrict__ pF, const float* __restrict__ P0,
    const uint2* __restrict__ veF, const float* __restrict__ VT,
    float* __restrict__ O)
{
    PIPE_SMEM;
    const int b = blockIdx.z;
    const int bm = b * Ss + blockIdx.y * 128;
    const int bn = blockIdx.x * 128;
    WARP_IDS;
    const char* aPtr = (const char*)pF + (size_t)(bm / 16) * 1024 + tid * 32;
    const char* bPtr = (const char*)veF
        + ((size_t)(b * Ee / 16) * (Hh / 8) + bn / 8) * 512 + tid * 32;
    const size_t aStride = (size_t)(BS / 16) * 1024;
    const size_t bStride = (size_t)(Hh / 8) * 512;

    ACC_INIT;
    PIPE_MAINLOOP(Ee / 16);

    #pragma unroll
    for (int mt = 0; mt < 4; mt++) {
        int r0 = bm + wm * 64 + mt * 16 + gid;
        int r1 = r0 + 8;
        float p0 = P0[r0];
        float p1 = P0[r1];
        #pragma unroll
        for (int nt = 0; nt < 4; nt++) {
            int col = bn + wn * 32 + nt * 8 + 2 * tg;
            float2 v0 = *(const float2*)(VT + (size_t)r0 * Hh + col);
            float2 v1 = *(const float2*)(VT + (size_t)r1 * Hh + col);
            float2 o0 = make_float2(fmaf(p0, v0.x, acc[mt][nt][0]),
                                    fmaf(p0, v0.y, acc[mt][nt][1]));
            float2 o1 = make_float2(fmaf(p1, v1.x, acc[mt][nt][2]),
                                    fmaf(p1, v1.y, acc[mt][nt][3]));
            *(float2*)(O + (size_t)r0 * Hh + col) = o0;
            *(float2*)(O + (size_t)r1 * Hh + col) = o1;
        }
    }
}

// ---------------------------------------------------------------------------
// Self-dot + softmax (softmax scatters probs into A-frag layout)
// ---------------------------------------------------------------------------
__global__ void self_dot_kernel(const float* __restrict__ q,
                                const float* __restrict__ kt,
                                float* __restrict__ S0)
{
    int row  = blockIdx.x * 8 + (threadIdx.x >> 5);
    int lane = threadIdx.x & 31;
    const float4* q4 = (const float4*)(q  + (size_t)row * Hh);
    const float4* k4 = (const float4*)(kt + (size_t)row * Hh);
    float sum = 0.f;
    #pragma unroll
    for (int i = lane; i < Hh / 4; i += 32) {
        float4 a = q4[i], b = k4[i];
        sum += a.x * b.x + a.y * b.y + a.z * b.z + a.w * b.w;
    }
    #pragma unroll
    for (int o = 16; o; o >>= 1) sum += __shfl_xor_sync(0xffffffffu, sum, o);
    if (lane == 0) S0[row] = sum;
}

__global__ void softmax_kernel(const float* __restrict__ SC,
                               float* __restrict__ S0,
                               uint32_t* __restrict__ PF)
{
    const int row = blockIdx.x;
    const float* s = SC + (size_t)row * 512;
    const int tid = threadIdx.x;
    __shared__ float redm[4], reds[4];

    float4 v = ((const float4*)s)[tid];
    float s0 = S0[row];
    float lmax = fmaxf(fmaxf(v.x, v.y), fmaxf(v.z, v.w));
    if (tid == 0) lmax = fmaxf(lmax, s0);
    #pragma unroll
    for (int o = 16; o; o >>= 1)
        lmax = fmaxf(lmax, __shfl_xor_sync(0xffffffffu, lmax, o));
    if ((tid & 31) == 0) redm[tid >> 5] = lmax;
    __syncthreads();
    float m = fmaxf(fmaxf(redm[0], redm[1]), fmaxf(redm[2], redm[3]));

    v.x = expf(v.x - m); v.y = expf(v.y - m);
    v.z = expf(v.z - m); v.w = expf(v.w - m);
    float e0 = expf(s0 - m);
    float lsum = v.x + v.y + v.z + v.w + ((tid == 0) ? e0 : 0.f);
    #pragma unroll
    for (int o = 16; o; o >>= 1) lsum += __shfl_xor_sync(0xffffffffu, lsum, o);
    if ((tid & 31) == 0) reds[tid >> 5] = lsum;
    __syncthreads();
    float inv = 1.f / (reds[0] + reds[1] + reds[2] + reds[3]);

    uint32_t h[2], l[2];
    split2(v.x * inv, v.y * inv, h[0], l[0]);
    split2(v.z * inv, v.w * inv, h[1], l[1]);

    const int m16 = row >> 4, gid = row & 7, mhalf = (row >> 3) & 1;
    #pragma unroll
    for (int qq = 0; qq < 2; qq++) {
        int kp = 2 * tid + qq;
        int kc = kp >> 3, tg = kp & 3, khalf = (kp >> 2) & 1;
        int lane = gid * 4 + tg, comp = mhalf + 2 * khalf;
        size_t gb = (size_t)kc * (BS / 16) + m16;
        PF[(gb * 64 + lane) * 4 + comp]      = h[qq];
        PF[(gb * 64 + 32 + lane) * 4 + comp] = l[qq];
    }
    if (tid == 0) S0[row] = e0 * inv;
}

// ---------------------------------------------------------------------------
extern "C" void kernel_launch(void* const* d_in, const int* in_sizes, int n_in,
                              void* d_out, int out_size)
{
    const float* hs  = (const float*)d_in[0];
    const float* ext = (const float*)d_in[1];
    const float* Wq  = (const float*)d_in[2];
    const float* bq  = (const float*)d_in[3];
    const float* Wk  = (const float*)d_in[4];
    const float* bk  = (const float*)d_in[5];
    const float* Wv  = (const float*)d_in[6];
    const float* bv  = (const float*)d_in[7];
    float* out = (float*)d_out;

    float *q, *kt, *vt, *ke, *ve, *sc, *s0;
    uint4 *hsF, *exF, *qF, *pF;
    uint2 *wF, *keF, *veF;
    cudaGetSymbolAddress((void**)&q,   g_q);
    cudaGetSymbolAddress((void**)&kt,  g_kt);
    cudaGetSymbolAddress((void**)&vt,  g_vt);
    cudaGetSymbolAddress((void**)&ke,  g_ke);
    cudaGetSymbolAddress((void**)&ve,  g_ve);
    cudaGetSymbolAddress((void**)&sc,  g_sc);
    cudaGetSymbolAddress((void**)&s0,  g_s0);
    cudaGetSymbolAddress((void**)&hsF, g_hsF);
    cudaGetSymbolAddress((void**)&exF, g_exF);
    cudaGetSymbolAddress((void**)&qF,  g_qF);
    cudaGetSymbolAddress((void**)&pF,  g_pF);
    cudaGetSymbolAddress((void**)&wF,  g_wF);
    cudaGetSymbolAddress((void**)&keF, g_keF);
    cudaGetSymbolAddress((void**)&veF, g_veF);

    cudaFuncSetAttribute(gemm_proj_all,
        cudaFuncAttributeMaxDynamicSharedMemorySize, SMEM_GEMM);
    cudaFuncSetAttribute(gemm_scores,
        cudaFuncAttributeMaxDynamicSharedMemorySize, SMEM_GEMM);
    cudaFuncSetAttribute(gemm_ctx,
        cudaFuncAttributeMaxDynamicSharedMemorySize, SMEM_GEMM);

    const size_t WFOFF = (size_t)(Hh / 16) * (Hh / 8) * 64;   // uint2 per weight

    // Pre-convert inputs into fragment-major layouts
    conv_A<<<dim3(BS / 64, Hh / 64), 256>>>(hs,  hsF, BS, Hh);
    conv_A<<<dim3(BE / 64, Hh / 64), 256>>>(ext, exF, BE, Hh);
    conv_B<<<dim3(Hh / 64, Hh / 64), 256>>>(Wq, wF,             Hh, Hh, WSCALE);
    conv_B<<<dim3(Hh / 64, Hh / 64), 256>>>(Wk, wF + WFOFF,     Hh, Hh, WSCALE);
    conv_B<<<dim3(Hh / 64, Hh / 64), 256>>>(Wv, wF + 2 * WFOFF, Hh, Hh, WSCALE);

    // All 5 projections, one launch
    gemm_proj_all<<<dim3(8, BS / 128, 5), 256, SMEM_GEMM>>>(
        hsF, exF, wF, bq, bk, bv, q, kt, vt, ke, ve);

    // Convert activations for scores / ctx
    conv_A<<<dim3(BS / 64, Hh / 64), 256>>>(q, qF, BS, Hh);
    conv_BT<<<dim3(BE / 64, Hh / 64), 256>>>(ke, keF, BE, Hh);
    conv_B<<<dim3(Hh / 64, BE / 64), 256>>>(ve, veF, BE, Hh, 1.0f);

    // Scores
    self_dot_kernel<<<BS / 8, 256>>>(q, kt, s0);
    gemm_scores<<<dim3(4, Ss / 128, Bb), 256, SMEM_GEMM>>>(qF, keF, sc);

    // Softmax (emits fragment-major probs)
    softmax_kernel<<<BS, 128>>>(sc, s0, (uint32_t*)pF);

    // Context
    gemm_ctx<<<dim3(8, Ss / 128, Bb), 256, SMEM_GEMM>>>(pF, s0, veF, vt, out);
}